// round 10
// baseline (speedup 1.0000x reference)
#include <cuda_runtime.h>
#include <cstdint>
#include <stdint.h>
#include <math.h>

#define N_NODES 20000
#define N_EDGES 320000
#define DMAX    512

// ---------------- scratch (static device globals; no allocation allowed) ----
__device__ __align__(16) float g_xl[N_NODES * DMAX];
__device__ __align__(16) float g_xr[N_NODES * DMAX];
__device__ __align__(16) float g_sk[N_NODES * DMAX];
__device__ __align__(16) float g_h1[N_NODES * 512];   // tf32-rounded at write
__device__ __align__(16) float g_h2[N_NODES * 256];   // tf32-rounded at write
__device__ __align__(16) float g_xa[N_NODES * 256];   // tf32-rounded copy of x
__device__ __align__(16) float g_wt[900000];          // tf32-rounded weights (884736 used)
__device__ int   g_srcs [N_EDGES];
__device__ int   g_count [N_NODES];
__device__ int   g_cursor[N_NODES];
__device__ int   g_rowptr[N_NODES + 1];

__device__ __forceinline__ float tf32r(float x) {
    uint32_t r;
    asm("cvt.rna.tf32.f32 %0, %1;" : "=r"(r) : "f"(x));
    return __uint_as_float(r);
}

// ---------------- merged tf32 rounding prepass (1 launch, 10 slices) --------
struct RConv {
    const float* src[10];
    float*       dst[10];
    int          n4[10];
};

__global__ void round_all_kernel(RConv rc) {
    int s = blockIdx.y;
    int n4 = rc.n4[s];
    const float4* in  = (const float4*)rc.src[s];
    float4*       out = (float4*)rc.dst[s];
    for (int i = blockIdx.x * blockDim.x + threadIdx.x; i < n4; i += gridDim.x * blockDim.x) {
        float4 v = in[i];
        v.x = tf32r(v.x); v.y = tf32r(v.y); v.z = tf32r(v.z); v.w = tf32r(v.w);
        out[i] = v;
    }
}

// ---------------- CSR build (counting sort by dst) --------------------------
__global__ void zero_counts_kernel() {
    int i = blockIdx.x * blockDim.x + threadIdx.x;
    if (i < N_NODES) { g_count[i] = 0; g_cursor[i] = 0; }
}

__global__ void hist_kernel(const int* __restrict__ dst) {
    int e = blockIdx.x * blockDim.x + threadIdx.x;
    if (e < N_EDGES) atomicAdd(&g_count[dst[e]], 1);
}

__global__ void scan_kernel() {
    __shared__ int part[1024];
    const int n = N_NODES;
    int tid = threadIdx.x;
    int chunk = (n + 1023) / 1024;
    int beg = tid * chunk;
    int end = min(beg + chunk, n);
    int sum = 0;
    for (int i = beg; i < end; i++) sum += g_count[i];
    part[tid] = sum;
    __syncthreads();
    for (int off = 1; off < 1024; off <<= 1) {
        int v = (tid >= off) ? part[tid - off] : 0;
        __syncthreads();
        part[tid] += v;
        __syncthreads();
    }
    int run = (tid > 0) ? part[tid - 1] : 0;
    for (int i = beg; i < end; i++) {
        int c = g_count[i];
        g_rowptr[i] = run;
        run += c;
    }
    if (tid == 1023) g_rowptr[n] = run;
}

__global__ void scatter_kernel(const int* __restrict__ src, const int* __restrict__ dst) {
    int e = blockIdx.x * blockDim.x + threadIdx.x;
    if (e < N_EDGES) {
        int d = dst[e];
        int pos = g_rowptr[d] + atomicAdd(&g_cursor[d], 1);
        g_srcs[pos] = src[e];
    }
}

// ---------------- TF32 mma.sync GEMM (z-batched over 3 weight mats) ---------
// CTA tile 256x128x16, 8 warps (4m x 2n), warp tile 64x64, mma.m16n8k8 tf32.
// 2-stage cp.async pipeline, dynamic smem. Inputs pre-rounded to tf32.
#define BM 256
#define BN 128
#define BK 16
#define AP (BK + 4)
#define BP (BN + 8)
#define GEMM_SMEM_BYTES (2 * (BM * AP + BK * BP) * 4)   // 58368

__device__ __forceinline__ void cpasync16(void* smem, const void* g, int sz) {
    uint32_t sa = (uint32_t)__cvta_generic_to_shared(smem);
    asm volatile("cp.async.cg.shared.global [%0], [%1], 16, %2;\n"
                 :: "r"(sa), "l"(g), "r"(sz));
}

__global__ __launch_bounds__(256, 1)
void gemm_tf32_b3_kernel(const float* __restrict__ A,
                         const float* __restrict__ B0, const float* __restrict__ B1,
                         const float* __restrict__ B2,
                         float* __restrict__ C0, float* __restrict__ C1,
                         float* __restrict__ C2,
                         int M, int N, int K) {
    const float* B = (blockIdx.z == 0) ? B0 : (blockIdx.z == 1) ? B1 : B2;
    float*       C = (blockIdx.z == 0) ? C0 : (blockIdx.z == 1) ? C1 : C2;

    extern __shared__ float smemBuf[];
    float (*As)[BM][AP] = (float (*)[BM][AP])smemBuf;
    float (*Bs)[BK][BP] = (float (*)[BK][BP])(smemBuf + 2 * BM * AP);

    int tid  = threadIdx.x;
    int warp = tid >> 5;
    int lane = tid & 31;
    int blockRow = blockIdx.y * BM;
    int blockCol = blockIdx.x * BN;
    int wm = (warp >> 1) * 64;   // warp m offset (4 warps in m)
    int wn = (warp & 1) * 64;    // warp n offset (2 warps in n)

    float acc[4][8][4];
#pragma unroll
    for (int i = 0; i < 4; i++)
#pragma unroll
        for (int j = 0; j < 8; j++)
#pragma unroll
            for (int t = 0; t < 4; t++) acc[i][j][t] = 0.f;

    // A: 256 rows x 4 float4 = 1024 chunks (4/thread); B: 16 rows x 32 float4 (2/thread)
    auto loadStage = [&](int s, int k0) {
#pragma unroll
        for (int j = 0; j < 4; j++) {
            int c = tid + j * 256;
            int row = c >> 2;
            int col = (c & 3) * 4;
            int gRow = blockRow + row;
            int ok = (gRow < M);
            const float* gp = A + (size_t)(ok ? gRow : 0) * K + k0 + col;
            cpasync16(&As[s][row][col], gp, ok ? 16 : 0);
        }
#pragma unroll
        for (int j = 0; j < 2; j++) {
            int c = tid + j * 256;
            int k = c >> 5;
            int col = (c & 31) * 4;
            const float* gp = B + (size_t)(k0 + k) * N + blockCol + col;
            cpasync16(&Bs[s][k][col], gp, 16);
        }
        asm volatile("cp.async.commit_group;\n");
    };

    int nK = K / BK;
    loadStage(0, 0);

    for (int kt = 0; kt < nK; kt++) {
        int s = kt & 1;
        if (kt + 1 < nK) {
            loadStage(s ^ 1, (kt + 1) * BK);
            asm volatile("cp.async.wait_group 1;\n");
        } else {
            asm volatile("cp.async.wait_group 0;\n");
        }
        __syncthreads();

#pragma unroll
        for (int ks = 0; ks < 2; ks++) {
            int kb = ks * 8;
            uint32_t aF[4][4];
#pragma unroll
            for (int i = 0; i < 4; i++) {
                int r0 = wm + i * 16 + (lane >> 2);
                int c0 = kb + (lane & 3);
                aF[i][0] = __float_as_uint(As[s][r0][c0]);
                aF[i][1] = __float_as_uint(As[s][r0 + 8][c0]);
                aF[i][2] = __float_as_uint(As[s][r0][c0 + 4]);
                aF[i][3] = __float_as_uint(As[s][r0 + 8][c0 + 4]);
            }
            uint32_t bF[8][2];
#pragma unroll
            for (int j = 0; j < 8; j++) {
                int kr = kb + (lane & 3);
                int nc = wn + j * 8 + (lane >> 2);
                bF[j][0] = __float_as_uint(Bs[s][kr][nc]);
                bF[j][1] = __float_as_uint(Bs[s][kr + 4][nc]);
            }
#pragma unroll
            for (int i = 0; i < 4; i++)
#pragma unroll
                for (int j = 0; j < 8; j++) {
                    asm volatile(
                        "mma.sync.aligned.m16n8k8.row.col.f32.tf32.tf32.f32 "
                        "{%0,%1,%2,%3}, {%4,%5,%6,%7}, {%8,%9}, {%0,%1,%2,%3};\n"
                        : "+f"(acc[i][j][0]), "+f"(acc[i][j][1]),
                          "+f"(acc[i][j][2]), "+f"(acc[i][j][3])
                        : "r"(aF[i][0]), "r"(aF[i][1]), "r"(aF[i][2]), "r"(aF[i][3]),
                          "r"(bF[j][0]), "r"(bF[j][1]));
                }
        }
        __syncthreads();
    }

#pragma unroll
    for (int i = 0; i < 4; i++) {
#pragma unroll
        for (int j = 0; j < 8; j++) {
            int r0 = blockRow + wm + i * 16 + (lane >> 2);
            int c0 = blockCol + wn + j * 8 + (lane & 3) * 2;
            if (r0 < M) {
                float2 v = make_float2(acc[i][j][0], acc[i][j][1]);
                *(float2*)(C + (size_t)r0 * N + c0) = v;
            }
            if (r0 + 8 < M) {
                float2 v = make_float2(acc[i][j][2], acc[i][j][3]);
                *(float2*)(C + (size_t)(r0 + 8) * N + c0) = v;
            }
        }
    }
}

// ---------------- fused edge phase: score + online softmax + aggregate ------
template <int NK4>   // float4 chunks per lane; D = NK4*128
__global__ void gat_edge_fused_kernel(const float* __restrict__ xl,
                                      const float* __restrict__ xr,
                                      const float* __restrict__ att,
                                      const float* __restrict__ sk,
                                      const float* __restrict__ bc,
                                      const float* __restrict__ bs,
                                      float* __restrict__ out,
                                      int doRelu, int roundOut) {
    const int D = NK4 * 128;
    int v = (blockIdx.x * blockDim.x + threadIdx.x) >> 5;
    if (v >= N_NODES) return;
    int lane = threadIdx.x & 31;
    int beg = g_rowptr[v], end = g_rowptr[v + 1];

    const float4* xr4  = (const float4*)(xr + (size_t)v * D);
    const float4* att4 = (const float4*)att;
    float4 xrv[NK4], atv[NK4], acc[NK4];
#pragma unroll
    for (int k = 0; k < NK4; k++) {
        xrv[k] = xr4[lane + 32 * k];
        atv[k] = att4[lane + 32 * k];
        acc[k] = make_float4(0.f, 0.f, 0.f, 0.f);
    }

    float m = -INFINITY, ssum = 0.f;
    for (int i = beg; i < end; i++) {
        int s = g_srcs[i];   // uniform across warp
        const float4* xs = (const float4*)(xl + (size_t)s * D);
        float4 vx[NK4];
#pragma unroll
        for (int k = 0; k < NK4; k++) vx[k] = xs[lane + 32 * k];

        float sc = 0.f;
#pragma unroll
        for (int k = 0; k < NK4; k++) {
            float t;
            t = vx[k].x + xrv[k].x; sc = fmaf((t > 0.f ? t : 0.2f * t), atv[k].x, sc);
            t = vx[k].y + xrv[k].y; sc = fmaf((t > 0.f ? t : 0.2f * t), atv[k].y, sc);
            t = vx[k].z + xrv[k].z; sc = fmaf((t > 0.f ? t : 0.2f * t), atv[k].z, sc);
            t = vx[k].w + xrv[k].w; sc = fmaf((t > 0.f ? t : 0.2f * t), atv[k].w, sc);
        }
#pragma unroll
        for (int off = 16; off > 0; off >>= 1)
            sc += __shfl_xor_sync(0xFFFFFFFFu, sc, off);

        float mn = fmaxf(m, sc);
        float scale = __expf(m - mn);   // first iter: exp(-inf)=0
        float w = __expf(sc - mn);
        ssum = ssum * scale + w;
#pragma unroll
        for (int k = 0; k < NK4; k++) {
            acc[k].x = fmaf(acc[k].x, scale, w * vx[k].x);
            acc[k].y = fmaf(acc[k].y, scale, w * vx[k].y);
            acc[k].z = fmaf(acc[k].z, scale, w * vx[k].z);
            acc[k].w = fmaf(acc[k].w, scale, w * vx[k].w);
        }
        m = mn;
    }

    float inv = 1.f / (ssum + 1e-16f);
    const float4* bc4 = (const float4*)bc;
    const float4* bs4 = (const float4*)bs;
    const float4* sk4 = (const float4*)(sk + (size_t)v * D);
    float4* out4 = (float4*)(out + (size_t)v * D);
#pragma unroll
    for (int k = 0; k < NK4; k++) {
        int idx = lane + 32 * k;
        float4 vbc = bc4[idx], vbs = bs4[idx], vsk = sk4[idx];
        float4 o;
        o.x = fmaf(acc[k].x, inv, vbc.x + vbs.x + vsk.x);
        o.y = fmaf(acc[k].y, inv, vbc.y + vbs.y + vsk.y);
        o.z = fmaf(acc[k].z, inv, vbc.z + vbs.z + vsk.z);
        o.w = fmaf(acc[k].w, inv, vbc.w + vbs.w + vsk.w);
        if (doRelu) {
            o.x = fmaxf(o.x, 0.f); o.y = fmaxf(o.y, 0.f);
            o.z = fmaxf(o.z, 0.f); o.w = fmaxf(o.w, 0.f);
        }
        if (roundOut) {
            o.x = tf32r(o.x); o.y = tf32r(o.y);
            o.z = tf32r(o.z); o.w = tf32r(o.w);
        }
        out4[idx] = o;
    }
}

// ---------------- host-side orchestration -----------------------------------
static void run_layer(const float* A, int K, int D,
                      const float* Wl, const float* Wr, const float* Ws,
                      const float* att, const float* bc, const float* bs,
                      float* out, int doRelu, int roundOut,
                      float* xl, float* xr, float* sk) {
    dim3 gg(D / BN, (N_NODES + BM - 1) / BM, 3);
    gemm_tf32_b3_kernel<<<gg, 256, GEMM_SMEM_BYTES>>>(A, Wl, Wr, Ws, xl, xr, sk, N_NODES, D, K);

    int warpsPerBlock = 8;
    int nbv = (N_NODES + warpsPerBlock - 1) / warpsPerBlock;
    if (D == 512)
        gat_edge_fused_kernel<4><<<nbv, warpsPerBlock * 32>>>(xl, xr, att, sk, bc, bs, out, doRelu, roundOut);
    else if (D == 256)
        gat_edge_fused_kernel<2><<<nbv, warpsPerBlock * 32>>>(xl, xr, att, sk, bc, bs, out, doRelu, roundOut);
    else
        gat_edge_fused_kernel<1><<<nbv, warpsPerBlock * 32>>>(xl, xr, att, sk, bc, bs, out, doRelu, roundOut);
}

extern "C" void kernel_launch(void* const* d_in, const int* in_sizes, int n_in,
                              void* d_out, int out_size) {
    const float* x  = (const float*)d_in[0];
    const int*   ei = (const int*)d_in[1];
    const int* src = ei;
    const int* dst = ei + N_EDGES;

    const float* Wl[3]  = {(const float*)d_in[2],  (const float*)d_in[8],  (const float*)d_in[14]};
    const float* Wr[3]  = {(const float*)d_in[3],  (const float*)d_in[9],  (const float*)d_in[15]};
    const float* att[3] = {(const float*)d_in[4],  (const float*)d_in[10], (const float*)d_in[16]};
    const float* bc[3]  = {(const float*)d_in[5],  (const float*)d_in[11], (const float*)d_in[17]};
    const float* Ws[3]  = {(const float*)d_in[6],  (const float*)d_in[12], (const float*)d_in[18]};
    const float* bs[3]  = {(const float*)d_in[7],  (const float*)d_in[13], (const float*)d_in[19]};

    float *xl, *xr, *sk, *h1, *h2, *xa, *wt;
    cudaGetSymbolAddress((void**)&xl, g_xl);
    cudaGetSymbolAddress((void**)&xr, g_xr);
    cudaGetSymbolAddress((void**)&sk, g_sk);
    cudaGetSymbolAddress((void**)&h1, g_h1);
    cudaGetSymbolAddress((void**)&h2, g_h2);
    cudaGetSymbolAddress((void**)&xa, g_xa);
    cudaGetSymbolAddress((void**)&wt, g_wt);

    (void)cudaFuncSetAttribute(gemm_tf32_b3_kernel,
                               cudaFuncAttributeMaxDynamicSharedMemorySize, GEMM_SMEM_BYTES);

    // tf32-rounded copies: 9 weight mats + x (ONE launch)
    int wn[9]  = {256*512, 256*512, 256*512, 512*256, 512*256, 512*256, 256*128, 256*128, 256*128};
    const float* wsrc[9] = {Wl[0], Wr[0], Ws[0], Wl[1], Wr[1], Ws[1], Wl[2], Wr[2], Ws[2]};
    float* wdst[9];
    {
        int off = 0;
        for (int i = 0; i < 9; i++) { wdst[i] = wt + off; off += wn[i]; }
    }
    RConv rc;
    for (int i = 0; i < 9; i++) {
        rc.src[i] = wsrc[i];
        rc.dst[i] = wdst[i];
        rc.n4[i]  = wn[i] / 4;
    }
    rc.src[9] = x; rc.dst[9] = xa; rc.n4[9] = N_NODES * 256 / 4;
    round_all_kernel<<<dim3(320, 10), 256>>>(rc);

    // CSR build (counting sort of edges by dst)
    zero_counts_kernel<<<(N_NODES + 255) / 256, 256>>>();
    hist_kernel<<<(N_EDGES + 255) / 256, 256>>>(dst);
    scan_kernel<<<1, 1024>>>();
    scatter_kernel<<<(N_EDGES + 255) / 256, 256>>>(src, dst);

    // Layer 1: 256 -> 512, relu, round for next GEMM
    run_layer(xa, 256, 512, wdst[0], wdst[1], wdst[2], att[0], bc[0], bs[0], h1, 1, 1, xl, xr, sk);
    // Layer 2: 512 -> 256, relu, round for next GEMM
    run_layer(h1, 512, 256, wdst[3], wdst[4], wdst[5], att[1], bc[1], bs[1], h2, 1, 1, xl, xr, sk);
    // Layer 3: 256 -> 128, no relu, full fp32 output
    run_layer(h2, 256, 128, wdst[6], wdst[7], wdst[8], att[2], bc[2], bs[2], (float*)d_out, 0, 0, xl, xr, sk);
}

// round 11
// speedup vs baseline: 1.0782x; 1.0782x over previous
#include <cuda_runtime.h>
#include <cstdint>
#include <stdint.h>
#include <math.h>

#define N_NODES 20000
#define N_EDGES 320000
#define DMAX    512

// ---------------- scratch (static device globals; no allocation allowed) ----
__device__ __align__(16) float g_xl[N_NODES * DMAX];
__device__ __align__(16) float g_xr[N_NODES * DMAX];
__device__ __align__(16) float g_sk[N_NODES * DMAX];
__device__ __align__(16) float g_h1[N_NODES * 512];   // tf32-rounded at write
__device__ __align__(16) float g_h2[N_NODES * 256];   // tf32-rounded at write
__device__ __align__(16) float g_xa[N_NODES * 256];   // tf32-rounded copy of x
__device__ __align__(16) float g_wt[900000];          // tf32-rounded weights (884736 used)
__device__ __align__(16) int   g_srcs [N_EDGES];
__device__ __align__(16) int   g_count [N_NODES];
__device__ __align__(16) int   g_cursor[N_NODES];
__device__ __align__(16) int   g_rowptr[N_NODES + 4];

__device__ __forceinline__ float tf32r(float x) {
    uint32_t r;
    asm("cvt.rna.tf32.f32 %0, %1;" : "=r"(r) : "f"(x));
    return __uint_as_float(r);
}

// ------- merged prepass: tf32-round 9 weights + x, zero count/cursor --------
struct RConv {
    const float* src[10];
    float*       dst[10];
    int          n4[10];
};

__global__ void round_all_kernel(RConv rc) {
    int s = blockIdx.y;
    if (s == 10) {   // zero g_count and g_cursor
        int4 z = make_int4(0, 0, 0, 0);
        for (int i = blockIdx.x * blockDim.x + threadIdx.x; i < N_NODES / 4;
             i += gridDim.x * blockDim.x) {
            ((int4*)g_count)[i]  = z;
            ((int4*)g_cursor)[i] = z;
        }
        return;
    }
    int n4 = rc.n4[s];
    const float4* in  = (const float4*)rc.src[s];
    float4*       out = (float4*)rc.dst[s];
    for (int i = blockIdx.x * blockDim.x + threadIdx.x; i < n4; i += gridDim.x * blockDim.x) {
        float4 v = in[i];
        v.x = tf32r(v.x); v.y = tf32r(v.y); v.z = tf32r(v.z); v.w = tf32r(v.w);
        out[i] = v;
    }
}

// ---------------- CSR build (counting sort by dst) --------------------------
__global__ void hist_kernel(const int* __restrict__ dst) {
    int e = blockIdx.x * blockDim.x + threadIdx.x;
    if (e < N_EDGES) atomicAdd(&g_count[dst[e]], 1);
}

// fast single-block scan: 1024 threads, 20 elems/thread (int4 loads),
// warp-shuffle hierarchical exclusive prefix
__global__ void scan_kernel() {
    const int CH = 20;                      // 1000 active threads cover 20000
    int tid = threadIdx.x;
    int lane = tid & 31, w = tid >> 5;
    int beg = tid * CH;
    int vals[CH];
    int sum = 0;
    if (beg < N_NODES) {
        const int4* p = (const int4*)(g_count + beg);   // beg % 4 == 0
#pragma unroll
        for (int i = 0; i < CH / 4; i++) {
            int4 v = p[i];
            vals[i * 4 + 0] = v.x; vals[i * 4 + 1] = v.y;
            vals[i * 4 + 2] = v.z; vals[i * 4 + 3] = v.w;
            sum += v.x + v.y + v.z + v.w;
        }
    }
    // inclusive scan of per-thread sums
    int inc = sum;
#pragma unroll
    for (int off = 1; off < 32; off <<= 1) {
        int t = __shfl_up_sync(0xFFFFFFFFu, inc, off);
        if (lane >= off) inc += t;
    }
    __shared__ int wsum[32];
    if (lane == 31) wsum[w] = inc;
    __syncthreads();
    if (w == 0) {
        int v = wsum[lane];
#pragma unroll
        for (int off = 1; off < 32; off <<= 1) {
            int t = __shfl_up_sync(0xFFFFFFFFu, v, off);
            if (lane >= off) v += t;
        }
        wsum[lane] = v;
    }
    __syncthreads();
    int base = (w > 0 ? wsum[w - 1] : 0) + inc - sum;   // exclusive prefix for this thread
    if (beg < N_NODES) {
        int run = base;
        int4* rp = (int4*)(g_rowptr + beg);
#pragma unroll
        for (int i = 0; i < CH / 4; i++) {
            int4 o;
            o.x = run; run += vals[i * 4 + 0];
            o.y = run; run += vals[i * 4 + 1];
            o.z = run; run += vals[i * 4 + 2];
            o.w = run; run += vals[i * 4 + 3];
            rp[i] = o;
        }
    }
    if (tid == 0) g_rowptr[N_NODES] = wsum[31];
}

__global__ void scatter_kernel(const int* __restrict__ src, const int* __restrict__ dst) {
    int e = blockIdx.x * blockDim.x + threadIdx.x;
    if (e < N_EDGES) {
        int d = dst[e];
        int pos = g_rowptr[d] + atomicAdd(&g_cursor[d], 1);
        g_srcs[pos] = src[e];
    }
}

// ---------------- TF32 mma.sync GEMM (z-batched over 3 weight mats) ---------
// CTA tile 128xBNv x16, 8 warps (4m x 2n), warp tile 32x(BNv/2), mma.m16n8k8.
// 3-stage cp.async pipeline, dynamic smem. Inputs pre-rounded to tf32.
#define BM 128
#define BK 16
#define AP (BK + 4)

__device__ __forceinline__ void cpasync16(void* smem, const void* g, int sz) {
    uint32_t sa = (uint32_t)__cvta_generic_to_shared(smem);
    asm volatile("cp.async.cg.shared.global [%0], [%1], 16, %2;\n"
                 :: "r"(sa), "l"(g), "r"(sz));
}

template <int BNv, int JN>      // JN = BNv/16 per warp (j-tiles of 8 wide, warp covers BNv/2)
__global__ __launch_bounds__(256, 2)
void gemm_tf32_b3_kernel(const float* __restrict__ A,
                         const float* __restrict__ B0, const float* __restrict__ B1,
                         const float* __restrict__ B2,
                         float* __restrict__ C0, float* __restrict__ C1,
                         float* __restrict__ C2,
                         int M, int N, int K) {
    const int BPv = BNv + 8;
    const float* B = (blockIdx.z == 0) ? B0 : (blockIdx.z == 1) ? B1 : B2;
    float*       C = (blockIdx.z == 0) ? C0 : (blockIdx.z == 1) ? C1 : C2;

    extern __shared__ float smemBuf[];
    float (*As)[BM][AP]  = (float (*)[BM][AP])smemBuf;
    float (*Bs)[BK][BPv] = (float (*)[BK][BPv])(smemBuf + 3 * BM * AP);

    int tid  = threadIdx.x;
    int warp = tid >> 5;
    int lane = tid & 31;
    int blockRow = blockIdx.y * BM;
    int blockCol = blockIdx.x * BNv;
    int wm = (warp >> 1) * 32;
    int wn = (warp & 1) * (JN * 8);

    float acc[2][JN][4];
#pragma unroll
    for (int i = 0; i < 2; i++)
#pragma unroll
        for (int j = 0; j < JN; j++)
#pragma unroll
            for (int t = 0; t < 4; t++) acc[i][j][t] = 0.f;

    auto loadStage = [&](int s, int k0) {
#pragma unroll
        for (int j = 0; j < 2; j++) {
            int c = tid + j * 256;
            int row = c >> 2;
            int col = (c & 3) * 4;
            int gRow = blockRow + row;
            int ok = (gRow < M);
            const float* gp = A + (size_t)(ok ? gRow : 0) * K + k0 + col;
            cpasync16(&As[s][row][col], gp, ok ? 16 : 0);
        }
#pragma unroll
        for (int j = 0; j < BNv / 64; j++) {
            int c = tid + j * 256;
            int k = c / (BNv / 4);
            int col = (c % (BNv / 4)) * 4;
            const float* gp = B + (size_t)(k0 + k) * N + blockCol + col;
            cpasync16(&Bs[s][k][col], gp, 16);
        }
        asm volatile("cp.async.commit_group;\n");
    };

    int nK = K / BK;          // >= 8 always here
    loadStage(0, 0);
    loadStage(1, BK);

    for (int kt = 0; kt < nK; kt++) {
        int s = kt % 3;
        if (kt + 2 < nK) {
            loadStage((kt + 2) % 3, (kt + 2) * BK);
            asm volatile("cp.async.wait_group 2;\n");
        } else if (kt + 1 < nK) {
            asm volatile("cp.async.wait_group 1;\n");
        } else {
            asm volatile("cp.async.wait_group 0;\n");
        }
        __syncthreads();

#pragma unroll
        for (int ks = 0; ks < 2; ks++) {
            int kb = ks * 8;
            uint32_t aF[2][4];
#pragma unroll
            for (int i = 0; i < 2; i++) {
                int r0 = wm + i * 16 + (lane >> 2);
                int c0 = kb + (lane & 3);
                aF[i][0] = __float_as_uint(As[s][r0][c0]);
                aF[i][1] = __float_as_uint(As[s][r0 + 8][c0]);
                aF[i][2] = __float_as_uint(As[s][r0][c0 + 4]);
                aF[i][3] = __float_as_uint(As[s][r0 + 8][c0 + 4]);
            }
            uint32_t bF[JN][2];
#pragma unroll
            for (int j = 0; j < JN; j++) {
                int kr = kb + (lane & 3);
                int nc = wn + j * 8 + (lane >> 2);
                bF[j][0] = __float_as_uint(Bs[s][kr][nc]);
                bF[j][1] = __float_as_uint(Bs[s][kr + 4][nc]);
            }
#pragma unroll
            for (int i = 0; i < 2; i++)
#pragma unroll
                for (int j = 0; j < JN; j++) {
                    asm volatile(
                        "mma.sync.aligned.m16n8k8.row.col.f32.tf32.tf32.f32 "
                        "{%0,%1,%2,%3}, {%4,%5,%6,%7}, {%8,%9}, {%0,%1,%2,%3};\n"
                        : "+f"(acc[i][j][0]), "+f"(acc[i][j][1]),
                          "+f"(acc[i][j][2]), "+f"(acc[i][j][3])
                        : "r"(aF[i][0]), "r"(aF[i][1]), "r"(aF[i][2]), "r"(aF[i][3]),
                          "r"(bF[j][0]), "r"(bF[j][1]));
                }
        }
        __syncthreads();
    }

#pragma unroll
    for (int i = 0; i < 2; i++) {
#pragma unroll
        for (int j = 0; j < JN; j++) {
            int r0 = blockRow + wm + i * 16 + (lane >> 2);
            int c0 = blockCol + wn + j * 8 + (lane & 3) * 2;
            if (r0 < M) {
                float2 v = make_float2(acc[i][j][0], acc[i][j][1]);
                *(float2*)(C + (size_t)r0 * N + c0) = v;
            }
            if (r0 + 8 < M) {
                float2 v = make_float2(acc[i][j][2], acc[i][j][3]);
                *(float2*)(C + (size_t)(r0 + 8) * N + c0) = v;
            }
        }
    }
}

#define GEMM_SMEM(BNv) (3 * (BM * AP + BK * ((BNv) + 8)) * 4)

// ---------------- fused edge phase: score + online softmax + aggregate ------
template <int NK4>   // float4 chunks per lane; D = NK4*128
__global__ void gat_edge_fused_kernel(const float* __restrict__ xl,
                                      const float* __restrict__ xr,
                                      const float* __restrict__ att,
                                      const float* __restrict__ sk,
                                      const float* __restrict__ bc,
                                      const float* __restrict__ bs,
                                      float* __restrict__ out,
                                      int doRelu, int roundOut) {
    const int D = NK4 * 128;
    int v = (blockIdx.x * blockDim.x + threadIdx.x) >> 5;
    if (v >= N_NODES) return;
    int lane = threadIdx.x & 31;
    int beg = g_rowptr[v], end = g_rowptr[v + 1];

    const float4* xr4  = (const float4*)(xr + (size_t)v * D);
    const float4* att4 = (const float4*)att;
    float4 xrv[NK4], atv[NK4], acc[NK4];
#pragma unroll
    for (int k = 0; k < NK4; k++) {
        xrv[k] = xr4[lane + 32 * k];
        atv[k] = att4[lane + 32 * k];
        acc[k] = make_float4(0.f, 0.f, 0.f, 0.f);
    }

    float m = -INFINITY, ssum = 0.f;
    for (int i = beg; i < end; i++) {
        int s = g_srcs[i];   // uniform across warp
        const float4* xs = (const float4*)(xl + (size_t)s * D);
        float4 vx[NK4];
#pragma unroll
        for (int k = 0; k < NK4; k++) vx[k] = xs[lane + 32 * k];

        float sc = 0.f;
#pragma unroll
        for (int k = 0; k < NK4; k++) {
            float t;
            t = vx[k].x + xrv[k].x; sc = fmaf((t > 0.f ? t : 0.2f * t), atv[k].x, sc);
            t = vx[k].y + xrv[k].y; sc = fmaf((t > 0.f ? t : 0.2f * t), atv[k].y, sc);
            t = vx[k].z + xrv[k].z; sc = fmaf((t > 0.f ? t : 0.2f * t), atv[k].z, sc);
            t = vx[k].w + xrv[k].w; sc = fmaf((t > 0.f ? t : 0.2f * t), atv[k].w, sc);
        }
#pragma unroll
        for (int off = 16; off > 0; off >>= 1)
            sc += __shfl_xor_sync(0xFFFFFFFFu, sc, off);

        float mn = fmaxf(m, sc);
        float scale = __expf(m - mn);   // first iter: exp(-inf)=0
        float w = __expf(sc - mn);
        ssum = ssum * scale + w;
#pragma unroll
        for (int k = 0; k < NK4; k++) {
            acc[k].x = fmaf(acc[k].x, scale, w * vx[k].x);
            acc[k].y = fmaf(acc[k].y, scale, w * vx[k].y);
            acc[k].z = fmaf(acc[k].z, scale, w * vx[k].z);
            acc[k].w = fmaf(acc[k].w, scale, w * vx[k].w);
        }
        m = mn;
    }

    float inv = 1.f / (ssum + 1e-16f);
    const float4* bc4 = (const float4*)bc;
    const float4* bs4 = (const float4*)bs;
    const float4* sk4 = (const float4*)(sk + (size_t)v * D);
    float4* out4 = (float4*)(out + (size_t)v * D);
#pragma unroll
    for (int k = 0; k < NK4; k++) {
        int idx = lane + 32 * k;
        float4 vbc = bc4[idx], vbs = bs4[idx], vsk = sk4[idx];
        float4 o;
        o.x = fmaf(acc[k].x, inv, vbc.x + vbs.x + vsk.x);
        o.y = fmaf(acc[k].y, inv, vbc.y + vbs.y + vsk.y);
        o.z = fmaf(acc[k].z, inv, vbc.z + vbs.z + vsk.z);
        o.w = fmaf(acc[k].w, inv, vbc.w + vbs.w + vsk.w);
        if (doRelu) {
            o.x = fmaxf(o.x, 0.f); o.y = fmaxf(o.y, 0.f);
            o.z = fmaxf(o.z, 0.f); o.w = fmaxf(o.w, 0.f);
        }
        if (roundOut) {
            o.x = tf32r(o.x); o.y = tf32r(o.y);
            o.z = tf32r(o.z); o.w = tf32r(o.w);
        }
        out4[idx] = o;
    }
}

// ---------------- host-side orchestration -----------------------------------
static void run_layer(const float* A, int K, int D,
                      const float* Wl, const float* Wr, const float* Ws,
                      const float* att, const float* bc, const float* bs,
                      float* out, int doRelu, int roundOut,
                      float* xl, float* xr, float* sk) {
    if (D >= 256) {
        dim3 gg(D / 128, (N_NODES + BM - 1) / BM, 3);
        gemm_tf32_b3_kernel<128, 8><<<gg, 256, GEMM_SMEM(128)>>>(
            A, Wl, Wr, Ws, xl, xr, sk, N_NODES, D, K);
    } else {
        dim3 gg(D / 64, (N_NODES + BM - 1) / BM, 3);
        gemm_tf32_b3_kernel<64, 4><<<gg, 256, GEMM_SMEM(64)>>>(
            A, Wl, Wr, Ws, xl, xr, sk, N_NODES, D, K);
    }

    int warpsPerBlock = 8;
    int nbv = (N_NODES + warpsPerBlock - 1) / warpsPerBlock;
    if (D == 512)
        gat_edge_fused_kernel<4><<<nbv, warpsPerBlock * 32>>>(xl, xr, att, sk, bc, bs, out, doRelu, roundOut);
    else if (D == 256)
        gat_edge_fused_kernel<2><<<nbv, warpsPerBlock * 32>>>(xl, xr, att, sk, bc, bs, out, doRelu, roundOut);
    else
        gat_edge_fused_kernel<1><<<nbv, warpsPerBlock * 32>>>(xl, xr, att, sk, bc, bs, out, doRelu, roundOut);
}

extern "C" void kernel_launch(void* const* d_in, const int* in_sizes, int n_in,
                              void* d_out, int out_size) {
    const float* x  = (const float*)d_in[0];
    const int*   ei = (const int*)d_in[1];
    const int* src = ei;
    const int* dst = ei + N_EDGES;

    const float* Wl[3]  = {(const float*)d_in[2],  (const float*)d_in[8],  (const float*)d_in[14]};
    const float* Wr[3]  = {(const float*)d_in[3],  (const float*)d_in[9],  (const float*)d_in[15]};
    const float* att[3] = {(const float*)d_in[4],  (const float*)d_in[10], (const float*)d_in[16]};
    const float* bc[3]  = {(const float*)d_in[5],  (const float*)d_in[11], (const float*)d_in[17]};
    const float* Ws[3]  = {(const float*)d_in[6],  (const float*)d_in[12], (const float*)d_in[18]};
    const float* bs[3]  = {(const float*)d_in[7],  (const float*)d_in[13], (const float*)d_in[19]};

    float *xl, *xr, *sk, *h1, *h2, *xa, *wt;
    cudaGetSymbolAddress((void**)&xl, g_xl);
    cudaGetSymbolAddress((void**)&xr, g_xr);
    cudaGetSymbolAddress((void**)&sk, g_sk);
    cudaGetSymbolAddress((void**)&h1, g_h1);
    cudaGetSymbolAddress((void**)&h2, g_h2);
    cudaGetSymbolAddress((void**)&xa, g_xa);
    cudaGetSymbolAddress((void**)&wt, g_wt);

    (void)cudaFuncSetAttribute(gemm_tf32_b3_kernel<128, 8>,
                               cudaFuncAttributeMaxDynamicSharedMemorySize, GEMM_SMEM(128));
    (void)cudaFuncSetAttribute(gemm_tf32_b3_kernel<64, 4>,
                               cudaFuncAttributeMaxDynamicSharedMemorySize, GEMM_SMEM(64));

    // merged prepass: 9 weights + x rounded, count/cursor zeroed (ONE launch)
    int wn[9]  = {256*512, 256*512, 256*512, 512*256, 512*256, 512*256, 256*128, 256*128, 256*128};
    const float* wsrc[9] = {Wl[0], Wr[0], Ws[0], Wl[1], Wr[1], Ws[1], Wl[2], Wr[2], Ws[2]};
    float* wdst[9];
    {
        int off = 0;
        for (int i = 0; i < 9; i++) { wdst[i] = wt + off; off += wn[i]; }
    }
    RConv rc;
    for (int i = 0; i < 9; i++) {
        rc.src[i] = wsrc[i];
        rc.dst[i] = wdst[i];
        rc.n4[i]  = wn[i] / 4;
    }
    rc.src[9] = x; rc.dst[9] = xa; rc.n4[9] = N_NODES * 256 / 4;
    round_all_kernel<<<dim3(320, 11), 256>>>(rc);

    // CSR build (counting sort of edges by dst)
    hist_kernel<<<(N_EDGES + 255) / 256, 256>>>(dst);
    scan_kernel<<<1, 1024>>>();
    scatter_kernel<<<(N_EDGES + 255) / 256, 256>>>(src, dst);

    // Layer 1: 256 -> 512, relu, round for next GEMM
    run_layer(xa, 256, 512, wdst[0], wdst[1], wdst[2], att[0], bc[0], bs[0], h1, 1, 1, xl, xr, sk);
    // Layer 2: 512 -> 256, relu, round for next GEMM
    run_layer(h1, 512, 256, wdst[3], wdst[4], wdst[5], att[1], bc[1], bs[1], h2, 1, 1, xl, xr, sk);
    // Layer 3: 256 -> 128, no relu, full fp32 output
    run_layer(h2, 256, 128, wdst[6], wdst[7], wdst[8], att[2], bc[2], bs[2], (float*)d_out, 0, 0, xl, xr, sk);
}

// round 12
// speedup vs baseline: 1.3993x; 1.2978x over previous
#include <cuda_runtime.h>
#include <cuda_fp16.h>
#include <cstdint>
#include <stdint.h>
#include <math.h>

#define N_NODES 20000
#define N_EDGES 320000
#define DMAX    512

// ---------------- scratch (static device globals; no allocation allowed) ----
__device__ __align__(16) float  g_xl[N_NODES * DMAX];
__device__ __align__(16) float  g_xr[N_NODES * DMAX];
__device__ __align__(16) float  g_sk[N_NODES * DMAX];
__device__ __align__(16) __half g_h1h[N_NODES * 512];   // fp16 activations (GEMM A input)
__device__ __align__(16) __half g_h2h[N_NODES * 256];
__device__ __align__(16) __half g_xah[N_NODES * 256];   // fp16 copy of x
__device__ __align__(16) __half g_wth[900000];          // fp16 transposed weights [N][K]
__device__ __align__(16) int    g_srcs [N_EDGES];
__device__ __align__(16) int    g_count [N_NODES];
__device__ __align__(16) int    g_cursor[N_NODES];
__device__ __align__(16) int    g_rowptr[N_NODES + 4];

// ------- merged prepass: transpose+fp16 9 weights, fp16 x, zero counts ------
struct PrepArgs {
    const float* wsrc[9];
    __half*      wdst[9];
    int          K[9], N[9];
    const float* xsrc;
    __half*      xdst;
    int          xn4;
};

__global__ void prep_kernel(PrepArgs pa) {
    int s = blockIdx.y;
    if (s == 9) {   // x -> fp16
        const float4* in = (const float4*)pa.xsrc;
        for (int i = blockIdx.x * blockDim.x + threadIdx.x; i < pa.xn4;
             i += gridDim.x * blockDim.x) {
            float4 v = in[i];
            __half2* o = (__half2*)(pa.xdst + (size_t)i * 4);
            o[0] = __floats2half2_rn(v.x, v.y);
            o[1] = __floats2half2_rn(v.z, v.w);
        }
        return;
    }
    if (s == 10) {  // zero count/cursor
        int4 z = make_int4(0, 0, 0, 0);
        for (int i = blockIdx.x * blockDim.x + threadIdx.x; i < N_NODES / 4;
             i += gridDim.x * blockDim.x) {
            ((int4*)g_count)[i]  = z;
            ((int4*)g_cursor)[i] = z;
        }
        return;
    }
    // transpose + convert: Wt[n][k] = fp16(W[k][n])
    int K = pa.K[s], N = pa.N[s];
    const float* src = pa.wsrc[s];
    __half*      dst = pa.wdst[s];
    int tpn = N / 32, tpk = K / 32, nt = tpn * tpk;
    __shared__ float tile[32][33];
    int tx = threadIdx.x & 31, ty = threadIdx.x >> 5;   // 32x8
    for (int t = blockIdx.x; t < nt; t += gridDim.x) {
        int n0 = (t % tpn) * 32, k0 = (t / tpn) * 32;
#pragma unroll
        for (int i = 0; i < 4; i++)
            tile[ty + 8 * i][tx] = src[(size_t)(k0 + ty + 8 * i) * N + n0 + tx];
        __syncthreads();
#pragma unroll
        for (int i = 0; i < 4; i++)
            dst[(size_t)(n0 + ty + 8 * i) * K + k0 + tx] = __float2half(tile[tx][ty + 8 * i]);
        __syncthreads();
    }
}

// ---------------- CSR build (counting sort by dst) --------------------------
__global__ void hist_kernel(const int* __restrict__ dst) {
    int e = blockIdx.x * blockDim.x + threadIdx.x;
    if (e < N_EDGES) atomicAdd(&g_count[dst[e]], 1);
}

__global__ void scan_kernel() {
    const int CH = 20;
    int tid = threadIdx.x;
    int lane = tid & 31, w = tid >> 5;
    int beg = tid * CH;
    int vals[CH];
    int sum = 0;
    if (beg < N_NODES) {
        const int4* p = (const int4*)(g_count + beg);
#pragma unroll
        for (int i = 0; i < CH / 4; i++) {
            int4 v = p[i];
            vals[i * 4 + 0] = v.x; vals[i * 4 + 1] = v.y;
            vals[i * 4 + 2] = v.z; vals[i * 4 + 3] = v.w;
            sum += v.x + v.y + v.z + v.w;
        }
    }
    int inc = sum;
#pragma unroll
    for (int off = 1; off < 32; off <<= 1) {
        int t = __shfl_up_sync(0xFFFFFFFFu, inc, off);
        if (lane >= off) inc += t;
    }
    __shared__ int wsum[32];
    if (lane == 31) wsum[w] = inc;
    __syncthreads();
    if (w == 0) {
        int v = wsum[lane];
#pragma unroll
        for (int off = 1; off < 32; off <<= 1) {
            int t = __shfl_up_sync(0xFFFFFFFFu, v, off);
            if (lane >= off) v += t;
        }
        wsum[lane] = v;
    }
    __syncthreads();
    int base = (w > 0 ? wsum[w - 1] : 0) + inc - sum;
    if (beg < N_NODES) {
        int run = base;
        int4* rp = (int4*)(g_rowptr + beg);
#pragma unroll
        for (int i = 0; i < CH / 4; i++) {
            int4 o;
            o.x = run; run += vals[i * 4 + 0];
            o.y = run; run += vals[i * 4 + 1];
            o.z = run; run += vals[i * 4 + 2];
            o.w = run; run += vals[i * 4 + 3];
            rp[i] = o;
        }
    }
    if (tid == 0) g_rowptr[N_NODES] = wsum[31];
}

__global__ void scatter_kernel(const int* __restrict__ src, const int* __restrict__ dst) {
    int e = blockIdx.x * blockDim.x + threadIdx.x;
    if (e < N_EDGES) {
        int d = dst[e];
        int pos = g_rowptr[d] + atomicAdd(&g_cursor[d], 1);
        g_srcs[pos] = src[e];
    }
}

// ---------------- FP16 mma.sync GEMM (z-batched over 3 weight mats) ---------
// C[M,N] = A[M,K] @ W[K,N].  A fp16 row-major; W pre-transposed fp16 [N][K].
// CTA tile 128 x BNv x 32, 8 warps (4m x 2n), mma.m16n8k16.f16 (fp32 accum).
// 3-stage cp.async pipeline, padded smem rows (40 halves) = conflict-free.
#define BM 128
#define GBK 32
#define APH 40

__device__ __forceinline__ void cpasync16(void* smem, const void* g, int sz) {
    uint32_t sa = (uint32_t)__cvta_generic_to_shared(smem);
    asm volatile("cp.async.cg.shared.global [%0], [%1], 16, %2;\n"
                 :: "r"(sa), "l"(g), "r"(sz));
}

template <int BNv, int JN>      // JN = BNv/16 (j-tiles of 8 per warp)
__global__ __launch_bounds__(256, 2)
void gemm_f16_b3_kernel(const __half* __restrict__ A,
                        const __half* __restrict__ W0, const __half* __restrict__ W1,
                        const __half* __restrict__ W2,
                        float* __restrict__ C0, float* __restrict__ C1,
                        float* __restrict__ C2,
                        int M, int N, int K) {
    const __half* Wt = (blockIdx.z == 0) ? W0 : (blockIdx.z == 1) ? W1 : W2;
    float*        C  = (blockIdx.z == 0) ? C0 : (blockIdx.z == 1) ? C1 : C2;

    extern __shared__ __half smemH[];
    __half (*As)[BM][APH]  = (__half (*)[BM][APH])smemH;
    __half (*Bs)[BNv][APH] = (__half (*)[BNv][APH])(smemH + 3 * BM * APH);

    int tid  = threadIdx.x;
    int warp = tid >> 5;
    int lane = tid & 31;
    int blockRow = blockIdx.y * BM;
    int blockCol = blockIdx.x * BNv;
    int wm = (warp >> 1) * 32;
    int wn = (warp & 1) * (JN * 8);

    float acc[2][JN][4];
#pragma unroll
    for (int i = 0; i < 2; i++)
#pragma unroll
        for (int j = 0; j < JN; j++)
#pragma unroll
            for (int t = 0; t < 4; t++) acc[i][j][t] = 0.f;

    auto loadStage = [&](int s, int k0) {
        // A: 128 rows x 4 chunks of 16B (8 halves)
#pragma unroll
        for (int j = 0; j < 2; j++) {
            int c = tid + j * 256;
            int row = c >> 2, part = c & 3;
            int gRow = blockRow + row;
            int ok = (gRow < M);
            const __half* gp = A + (size_t)(ok ? gRow : 0) * K + k0 + part * 8;
            cpasync16(&As[s][row][part * 8], gp, ok ? 16 : 0);
        }
        // B: BNv rows x 4 chunks of 16B
#pragma unroll
        for (int j = 0; j < BNv / 64; j++) {
            int c = tid + j * 256;
            int row = c >> 2, part = c & 3;
            const __half* gp = Wt + (size_t)(blockCol + row) * K + k0 + part * 8;
            cpasync16(&Bs[s][row][part * 8], gp, 16);
        }
        asm volatile("cp.async.commit_group;\n");
    };

    int nK = K / GBK;          // >= 4 always here
    loadStage(0, 0);
    loadStage(1, GBK);

    for (int kt = 0; kt < nK; kt++) {
        int s = kt % 3;
        if (kt + 2 < nK) {
            loadStage((kt + 2) % 3, (kt + 2) * GBK);
            asm volatile("cp.async.wait_group 2;\n");
        } else if (kt + 1 < nK) {
            asm volatile("cp.async.wait_group 1;\n");
        } else {
            asm volatile("cp.async.wait_group 0;\n");
        }
        __syncthreads();

#pragma unroll
        for (int ks = 0; ks < 2; ks++) {
            int kc = ks * 16 + (lane & 3) * 2;
            uint32_t aF[2][4];
#pragma unroll
            for (int i = 0; i < 2; i++) {
                int r0 = wm + i * 16 + (lane >> 2);
                aF[i][0] = *(const uint32_t*)&As[s][r0][kc];
                aF[i][1] = *(const uint32_t*)&As[s][r0 + 8][kc];
                aF[i][2] = *(const uint32_t*)&As[s][r0][kc + 8];
                aF[i][3] = *(const uint32_t*)&As[s][r0 + 8][kc + 8];
            }
            uint32_t bF[JN][2];
#pragma unroll
            for (int j = 0; j < JN; j++) {
                int nc = wn + j * 8 + (lane >> 2);
                bF[j][0] = *(const uint32_t*)&Bs[s][nc][kc];
                bF[j][1] = *(const uint32_t*)&Bs[s][nc][kc + 8];
            }
#pragma unroll
            for (int i = 0; i < 2; i++)
#pragma unroll
                for (int j = 0; j < JN; j++) {
                    asm volatile(
                        "mma.sync.aligned.m16n8k16.row.col.f32.f16.f16.f32 "
                        "{%0,%1,%2,%3}, {%4,%5,%6,%7}, {%8,%9}, {%0,%1,%2,%3};\n"
                        : "+f"(acc[i][j][0]), "+f"(acc[i][j][1]),
                          "+f"(acc[i][j][2]), "+f"(acc[i][j][3])
                        : "r"(aF[i][0]), "r"(aF[i][1]), "r"(aF[i][2]), "r"(aF[i][3]),
                          "r"(bF[j][0]), "r"(bF[j][1]));
                }
        }
        __syncthreads();
    }

#pragma unroll
    for (int i = 0; i < 2; i++) {
#pragma unroll
        for (int j = 0; j < JN; j++) {
            int r0 = blockRow + wm + i * 16 + (lane >> 2);
            int c0 = blockCol + wn + j * 8 + (lane & 3) * 2;
            if (r0 < M) {
                float2 v = make_float2(acc[i][j][0], acc[i][j][1]);
                *(float2*)(C + (size_t)r0 * N + c0) = v;
            }
            if (r0 + 8 < M) {
                float2 v = make_float2(acc[i][j][2], acc[i][j][3]);
                *(float2*)(C + (size_t)(r0 + 8) * N + c0) = v;
            }
        }
    }
}

#define GEMM_SMEM(BNv) (3 * (BM * APH + (BNv) * APH) * 2)

// ---------------- fused edge phase: score + online softmax + aggregate ------
// Writes fp16 (outh) for layers 1-2 (next GEMM's A input) or fp32 (out) layer 3.
template <int NK4>   // float4 chunks per lane; D = NK4*128
__global__ void gat_edge_fused_kernel(const float* __restrict__ xl,
                                      const float* __restrict__ xr,
                                      const float* __restrict__ att,
                                      const float* __restrict__ sk,
                                      const float* __restrict__ bc,
                                      const float* __restrict__ bs,
                                      float* __restrict__ out,
                                      __half* __restrict__ outh,
                                      int doRelu) {
    const int D = NK4 * 128;
    int v = (blockIdx.x * blockDim.x + threadIdx.x) >> 5;
    if (v >= N_NODES) return;
    int lane = threadIdx.x & 31;
    int beg = g_rowptr[v], end = g_rowptr[v + 1];

    const float4* xr4  = (const float4*)(xr + (size_t)v * D);
    const float4* att4 = (const float4*)att;
    float4 xrv[NK4], atv[NK4], acc[NK4];
#pragma unroll
    for (int k = 0; k < NK4; k++) {
        xrv[k] = xr4[lane + 32 * k];
        atv[k] = att4[lane + 32 * k];
        acc[k] = make_float4(0.f, 0.f, 0.f, 0.f);
    }

    float m = -INFINITY, ssum = 0.f;
    for (int i = beg; i < end; i++) {
        int s = g_srcs[i];   // uniform across warp
        const float4* xs = (const float4*)(xl + (size_t)s * D);
        float4 vx[NK4];
#pragma unroll
        for (int k = 0; k < NK4; k++) vx[k] = xs[lane + 32 * k];

        float sc = 0.f;
#pragma unroll
        for (int k = 0; k < NK4; k++) {
            float t;
            t = vx[k].x + xrv[k].x; sc = fmaf((t > 0.f ? t : 0.2f * t), atv[k].x, sc);
            t = vx[k].y + xrv[k].y; sc = fmaf((t > 0.f ? t : 0.2f * t), atv[k].y, sc);
            t = vx[k].z + xrv[k].z; sc = fmaf((t > 0.f ? t : 0.2f * t), atv[k].z, sc);
            t = vx[k].w + xrv[k].w; sc = fmaf((t > 0.f ? t : 0.2f * t), atv[k].w, sc);
        }
#pragma unroll
        for (int off = 16; off > 0; off >>= 1)
            sc += __shfl_xor_sync(0xFFFFFFFFu, sc, off);

        float mn = fmaxf(m, sc);
        float scale = __expf(m - mn);   // first iter: exp(-inf)=0
        float w = __expf(sc - mn);
        ssum = ssum * scale + w;
#pragma unroll
        for (int k = 0; k < NK4; k++) {
            acc[k].x = fmaf(acc[k].x, scale, w * vx[k].x);
            acc[k].y = fmaf(acc[k].y, scale, w * vx[k].y);
            acc[k].z = fmaf(acc[k].z, scale, w * vx[k].z);
            acc[k].w = fmaf(acc[k].w, scale, w * vx[k].w);
        }
        m = mn;
    }

    float inv = 1.f / (ssum + 1e-16f);
    const float4* bc4 = (const float4*)bc;
    const float4* bs4 = (const float4*)bs;
    const float4* sk4 = (const float4*)(sk + (size_t)v * D);
#pragma unroll
    for (int k = 0; k < NK4; k++) {
        int idx = lane + 32 * k;
        float4 vbc = bc4[idx], vbs = bs4[idx], vsk = sk4[idx];
        float4 o;
        o.x = fmaf(acc[k].x, inv, vbc.x + vbs.x + vsk.x);
        o.y = fmaf(acc[k].y, inv, vbc.y + vbs.y + vsk.y);
        o.z = fmaf(acc[k].z, inv, vbc.z + vbs.z + vsk.z);
        o.w = fmaf(acc[k].w, inv, vbc.w + vbs.w + vsk.w);
        if (doRelu) {
            o.x = fmaxf(o.x, 0.f); o.y = fmaxf(o.y, 0.f);
            o.z = fmaxf(o.z, 0.f); o.w = fmaxf(o.w, 0.f);
        }
        if (outh) {
            __half2* oh = (__half2*)(outh + (size_t)v * D) + idx * 2;
            oh[0] = __floats2half2_rn(o.x, o.y);
            oh[1] = __floats2half2_rn(o.z, o.w);
        } else {
            ((float4*)(out + (size_t)v * D))[idx] = o;
        }
    }
}

// ---------------- host-side orchestration -----------------------------------
static void run_layer(const __half* A, int K, int D,
                      const __half* Wt_l, const __half* Wt_r, const __half* Wt_s,
                      const float* att, const float* bc, const float* bs,
                      float* out, __half* outh, int doRelu,
                      float* xl, float* xr, float* sk) {
    if (D >= 256) {
        dim3 gg(D / 128, (N_NODES + BM - 1) / BM, 3);
        gemm_f16_b3_kernel<128, 8><<<gg, 256, GEMM_SMEM(128)>>>(
            A, Wt_l, Wt_r, Wt_s, xl, xr, sk, N_NODES, D, K);
    } else {
        dim3 gg(D / 64, (N_NODES + BM - 1) / BM, 3);
        gemm_f16_b3_kernel<64, 4><<<gg, 256, GEMM_SMEM(64)>>>(
            A, Wt_l, Wt_r, Wt_s, xl, xr, sk, N_NODES, D, K);
    }

    int warpsPerBlock = 8;
    int nbv = (N_NODES + warpsPerBlock - 1) / warpsPerBlock;
    if (D == 512)
        gat_edge_fused_kernel<4><<<nbv, warpsPerBlock * 32>>>(xl, xr, att, sk, bc, bs, out, outh, doRelu);
    else if (D == 256)
        gat_edge_fused_kernel<2><<<nbv, warpsPerBlock * 32>>>(xl, xr, att, sk, bc, bs, out, outh, doRelu);
    else
        gat_edge_fused_kernel<1><<<nbv, warpsPerBlock * 32>>>(xl, xr, att, sk, bc, bs, out, outh, doRelu);
}

extern "C" void kernel_launch(void* const* d_in, const int* in_sizes, int n_in,
                              void* d_out, int out_size) {
    const float* x  = (const float*)d_in[0];
    const int*   ei = (const int*)d_in[1];
    const int* src = ei;
    const int* dst = ei + N_EDGES;

    const float* Wl[3]  = {(const float*)d_in[2],  (const float*)d_in[8],  (const float*)d_in[14]};
    const float* Wr[3]  = {(const float*)d_in[3],  (const float*)d_in[9],  (const float*)d_in[15]};
    const float* att[3] = {(const float*)d_in[4],  (const float*)d_in[10], (const float*)d_in[16]};
    const float* bc[3]  = {(const float*)d_in[5],  (const float*)d_in[11], (const float*)d_in[17]};
    const float* Ws[3]  = {(const float*)d_in[6],  (const float*)d_in[12], (const float*)d_in[18]};
    const float* bs[3]  = {(const float*)d_in[7],  (const float*)d_in[13], (const float*)d_in[19]};

    float *xl, *xr, *sk;
    __half *h1h, *h2h, *xah, *wth;
    cudaGetSymbolAddress((void**)&xl,  g_xl);
    cudaGetSymbolAddress((void**)&xr,  g_xr);
    cudaGetSymbolAddress((void**)&sk,  g_sk);
    cudaGetSymbolAddress((void**)&h1h, g_h1h);
    cudaGetSymbolAddress((void**)&h2h, g_h2h);
    cudaGetSymbolAddress((void**)&xah, g_xah);
    cudaGetSymbolAddress((void**)&wth, g_wth);

    (void)cudaFuncSetAttribute(gemm_f16_b3_kernel<128, 8>,
                               cudaFuncAttributeMaxDynamicSharedMemorySize, GEMM_SMEM(128));
    (void)cudaFuncSetAttribute(gemm_f16_b3_kernel<64, 4>,
                               cudaFuncAttributeMaxDynamicSharedMemorySize, GEMM_SMEM(64));

    // merged prepass (one launch): transpose+fp16 weights, fp16 x, zero counts
    int wK[9] = {256, 256, 256, 512, 512, 512, 256, 256, 256};
    int wN[9] = {512, 512, 512, 256, 256, 256, 128, 128, 128};
    const float* wsrc[9] = {Wl[0], Wr[0], Ws[0], Wl[1], Wr[1], Ws[1], Wl[2], Wr[2], Ws[2]};
    __half* wdst[9];
    {
        int off = 0;
        for (int i = 0; i < 9; i++) { wdst[i] = wth + off; off += wK[i] * wN[i]; }
    }
    PrepArgs pa;
    for (int i = 0; i < 9; i++) {
        pa.wsrc[i] = wsrc[i]; pa.wdst[i] = wdst[i];
        pa.K[i] = wK[i]; pa.N[i] = wN[i];
    }
    pa.xsrc = x; pa.xdst = xah; pa.xn4 = N_NODES * 256 / 4;
    prep_kernel<<<dim3(160, 11), 256>>>(pa);

    // CSR build (counting sort of edges by dst)
    hist_kernel<<<(N_EDGES + 255) / 256, 256>>>(dst);
    scan_kernel<<<1, 1024>>>();
    scatter_kernel<<<(N_EDGES + 255) / 256, 256>>>(src, dst);

    // Layer 1: 256 -> 512, relu, fp16 out for next GEMM
    run_layer(xah, 256, 512, wdst[0], wdst[1], wdst[2], att[0], bc[0], bs[0],
              nullptr, h1h, 1, xl, xr, sk);
    // Layer 2: 512 -> 256, relu, fp16 out
    run_layer(h1h, 512, 256, wdst[3], wdst[4], wdst[5], att[1], bc[1], bs[1],
              nullptr, h2h, 1, xl, xr, sk);
    // Layer 3: 256 -> 128, no relu, fp32 output
    run_layer(h2h, 256, 128, wdst[6], wdst[7], wdst[8], att[2], bc[2], bs[2],
              (float*)d_out, nullptr, 0, xl, xr, sk);
}

// round 13
// speedup vs baseline: 1.4125x; 1.0094x over previous
#include <cuda_runtime.h>
#include <cuda_fp16.h>
#include <cstdint>
#include <stdint.h>
#include <math.h>

#define N_NODES 20000
#define N_EDGES 320000
#define DMAX    512

// ---------------- scratch (static device globals; no allocation allowed) ----
__device__ __align__(16) __half g_xlh[N_NODES * DMAX];  // fp16 xl (edge-gather operand)
__device__ __align__(16) float  g_xr[N_NODES * DMAX];
__device__ __align__(16) float  g_sk[N_NODES * DMAX];
__device__ __align__(16) __half g_h1h[N_NODES * 512];   // fp16 activations (GEMM A input)
__device__ __align__(16) __half g_h2h[N_NODES * 256];
__device__ __align__(16) __half g_xah[N_NODES * 256];   // fp16 copy of x
__device__ __align__(16) __half g_wth[900000];          // fp16 transposed weights [N][K]
__device__ __align__(16) int    g_srcs [N_EDGES];
__device__ __align__(16) int    g_count [N_NODES];
__device__ __align__(16) int    g_cursor[N_NODES];
__device__ __align__(16) int    g_rowptr[N_NODES + 4];

// ------- merged prepass: transpose+fp16 9 weights, fp16 x, zero counts ------
struct PrepArgs {
    const float* wsrc[9];
    __half*      wdst[9];
    int          K[9], N[9];
    const float* xsrc;
    __half*      xdst;
    int          xn4;
};

__global__ void prep_kernel(PrepArgs pa) {
    int s = blockIdx.y;
    if (s == 9) {   // x -> fp16
        const float4* in = (const float4*)pa.xsrc;
        for (int i = blockIdx.x * blockDim.x + threadIdx.x; i < pa.xn4;
             i += gridDim.x * blockDim.x) {
            float4 v = in[i];
            __half2* o = (__half2*)(pa.xdst + (size_t)i * 4);
            o[0] = __floats2half2_rn(v.x, v.y);
            o[1] = __floats2half2_rn(v.z, v.w);
        }
        return;
    }
    if (s == 10) {  // zero count/cursor
        int4 z = make_int4(0, 0, 0, 0);
        for (int i = blockIdx.x * blockDim.x + threadIdx.x; i < N_NODES / 4;
             i += gridDim.x * blockDim.x) {
            ((int4*)g_count)[i]  = z;
            ((int4*)g_cursor)[i] = z;
        }
        return;
    }
    // transpose + convert: Wt[n][k] = fp16(W[k][n])
    int K = pa.K[s], N = pa.N[s];
    const float* src = pa.wsrc[s];
    __half*      dst = pa.wdst[s];
    int tpn = N / 32, tpk = K / 32, nt = tpn * tpk;
    __shared__ float tile[32][33];
    int tx = threadIdx.x & 31, ty = threadIdx.x >> 5;   // 32x8
    for (int t = blockIdx.x; t < nt; t += gridDim.x) {
        int n0 = (t % tpn) * 32, k0 = (t / tpn) * 32;
#pragma unroll
        for (int i = 0; i < 4; i++)
            tile[ty + 8 * i][tx] = src[(size_t)(k0 + ty + 8 * i) * N + n0 + tx];
        __syncthreads();
#pragma unroll
        for (int i = 0; i < 4; i++)
            dst[(size_t)(n0 + ty + 8 * i) * K + k0 + tx] = __float2half(tile[tx][ty + 8 * i]);
        __syncthreads();
    }
}

// ---------------- CSR build (counting sort by dst) --------------------------
__global__ void hist_kernel(const int* __restrict__ dst) {
    int e = blockIdx.x * blockDim.x + threadIdx.x;
    if (e < N_EDGES) atomicAdd(&g_count[dst[e]], 1);
}

__global__ void scan_kernel() {
    const int CH = 20;
    int tid = threadIdx.x;
    int lane = tid & 31, w = tid >> 5;
    int beg = tid * CH;
    int vals[CH];
    int sum = 0;
    if (beg < N_NODES) {
        const int4* p = (const int4*)(g_count + beg);
#pragma unroll
        for (int i = 0; i < CH / 4; i++) {
            int4 v = p[i];
            vals[i * 4 + 0] = v.x; vals[i * 4 + 1] = v.y;
            vals[i * 4 + 2] = v.z; vals[i * 4 + 3] = v.w;
            sum += v.x + v.y + v.z + v.w;
        }
    }
    int inc = sum;
#pragma unroll
    for (int off = 1; off < 32; off <<= 1) {
        int t = __shfl_up_sync(0xFFFFFFFFu, inc, off);
        if (lane >= off) inc += t;
    }
    __shared__ int wsum[32];
    if (lane == 31) wsum[w] = inc;
    __syncthreads();
    if (w == 0) {
        int v = wsum[lane];
#pragma unroll
        for (int off = 1; off < 32; off <<= 1) {
            int t = __shfl_up_sync(0xFFFFFFFFu, v, off);
            if (lane >= off) v += t;
        }
        wsum[lane] = v;
    }
    __syncthreads();
    int base = (w > 0 ? wsum[w - 1] : 0) + inc - sum;
    if (beg < N_NODES) {
        int run = base;
        int4* rp = (int4*)(g_rowptr + beg);
#pragma unroll
        for (int i = 0; i < CH / 4; i++) {
            int4 o;
            o.x = run; run += vals[i * 4 + 0];
            o.y = run; run += vals[i * 4 + 1];
            o.z = run; run += vals[i * 4 + 2];
            o.w = run; run += vals[i * 4 + 3];
            rp[i] = o;
        }
    }
    if (tid == 0) g_rowptr[N_NODES] = wsum[31];
}

__global__ void scatter_kernel(const int* __restrict__ src, const int* __restrict__ dst) {
    int e = blockIdx.x * blockDim.x + threadIdx.x;
    if (e < N_EDGES) {
        int d = dst[e];
        int pos = g_rowptr[d] + atomicAdd(&g_cursor[d], 1);
        g_srcs[pos] = src[e];
    }
}

// ---------------- FP16 mma.sync GEMM (z-batched over 3 weight mats) ---------
// C = A @ W.  A fp16 row-major; W pre-transposed fp16 [N][K].
// z=0 writes fp16 (xl); z=1,2 write fp32 (xr, sk).
// CTA tile 128 x BNv x 32, 8 warps (4m x 2n), mma.m16n8k16.f16 (fp32 accum).
#define BM 128
#define GBK 32
#define APH 40

__device__ __forceinline__ void cpasync16(void* smem, const void* g, int sz) {
    uint32_t sa = (uint32_t)__cvta_generic_to_shared(smem);
    asm volatile("cp.async.cg.shared.global [%0], [%1], 16, %2;\n"
                 :: "r"(sa), "l"(g), "r"(sz));
}

template <int BNv, int JN>      // JN = BNv/16 (j-tiles of 8 per warp)
__global__ __launch_bounds__(256, 2)
void gemm_f16_b3_kernel(const __half* __restrict__ A,
                        const __half* __restrict__ W0, const __half* __restrict__ W1,
                        const __half* __restrict__ W2,
                        __half* __restrict__ C0h, float* __restrict__ C1,
                        float* __restrict__ C2,
                        int M, int N, int K) {
    const __half* Wt = (blockIdx.z == 0) ? W0 : (blockIdx.z == 1) ? W1 : W2;

    extern __shared__ __half smemH[];
    __half (*As)[BM][APH]  = (__half (*)[BM][APH])smemH;
    __half (*Bs)[BNv][APH] = (__half (*)[BNv][APH])(smemH + 3 * BM * APH);

    int tid  = threadIdx.x;
    int warp = tid >> 5;
    int lane = tid & 31;
    int blockRow = blockIdx.y * BM;
    int blockCol = blockIdx.x * BNv;
    int wm = (warp >> 1) * 32;
    int wn = (warp & 1) * (JN * 8);

    float acc[2][JN][4];
#pragma unroll
    for (int i = 0; i < 2; i++)
#pragma unroll
        for (int j = 0; j < JN; j++)
#pragma unroll
            for (int t = 0; t < 4; t++) acc[i][j][t] = 0.f;

    auto loadStage = [&](int s, int k0) {
#pragma unroll
        for (int j = 0; j < 2; j++) {
            int c = tid + j * 256;
            int row = c >> 2, part = c & 3;
            int gRow = blockRow + row;
            int ok = (gRow < M);
            const __half* gp = A + (size_t)(ok ? gRow : 0) * K + k0 + part * 8;
            cpasync16(&As[s][row][part * 8], gp, ok ? 16 : 0);
        }
#pragma unroll
        for (int j = 0; j < BNv / 64; j++) {
            int c = tid + j * 256;
            int row = c >> 2, part = c & 3;
            const __half* gp = Wt + (size_t)(blockCol + row) * K + k0 + part * 8;
            cpasync16(&Bs[s][row][part * 8], gp, 16);
        }
        asm volatile("cp.async.commit_group;\n");
    };

    int nK = K / GBK;
    loadStage(0, 0);
    loadStage(1, GBK);

    for (int kt = 0; kt < nK; kt++) {
        int s = kt % 3;
        if (kt + 2 < nK) {
            loadStage((kt + 2) % 3, (kt + 2) * GBK);
            asm volatile("cp.async.wait_group 2;\n");
        } else if (kt + 1 < nK) {
            asm volatile("cp.async.wait_group 1;\n");
        } else {
            asm volatile("cp.async.wait_group 0;\n");
        }
        __syncthreads();

#pragma unroll
        for (int ks = 0; ks < 2; ks++) {
            int kc = ks * 16 + (lane & 3) * 2;
            uint32_t aF[2][4];
#pragma unroll
            for (int i = 0; i < 2; i++) {
                int r0 = wm + i * 16 + (lane >> 2);
                aF[i][0] = *(const uint32_t*)&As[s][r0][kc];
                aF[i][1] = *(const uint32_t*)&As[s][r0 + 8][kc];
                aF[i][2] = *(const uint32_t*)&As[s][r0][kc + 8];
                aF[i][3] = *(const uint32_t*)&As[s][r0 + 8][kc + 8];
            }
            uint32_t bF[JN][2];
#pragma unroll
            for (int j = 0; j < JN; j++) {
                int nc = wn + j * 8 + (lane >> 2);
                bF[j][0] = *(const uint32_t*)&Bs[s][nc][kc];
                bF[j][1] = *(const uint32_t*)&Bs[s][nc][kc + 8];
            }
#pragma unroll
            for (int i = 0; i < 2; i++)
#pragma unroll
                for (int j = 0; j < JN; j++) {
                    asm volatile(
                        "mma.sync.aligned.m16n8k16.row.col.f32.f16.f16.f32 "
                        "{%0,%1,%2,%3}, {%4,%5,%6,%7}, {%8,%9}, {%0,%1,%2,%3};\n"
                        : "+f"(acc[i][j][0]), "+f"(acc[i][j][1]),
                          "+f"(acc[i][j][2]), "+f"(acc[i][j][3])
                        : "r"(aF[i][0]), "r"(aF[i][1]), "r"(aF[i][2]), "r"(aF[i][3]),
                          "r"(bF[j][0]), "r"(bF[j][1]));
                }
        }
        __syncthreads();
    }

    if (blockIdx.z == 0) {      // xl -> fp16
#pragma unroll
        for (int i = 0; i < 2; i++) {
#pragma unroll
            for (int j = 0; j < JN; j++) {
                int r0 = blockRow + wm + i * 16 + (lane >> 2);
                int c0 = blockCol + wn + j * 8 + (lane & 3) * 2;
                if (r0 < M)
                    *(__half2*)(C0h + (size_t)r0 * N + c0) =
                        __floats2half2_rn(acc[i][j][0], acc[i][j][1]);
                if (r0 + 8 < M)
                    *(__half2*)(C0h + (size_t)(r0 + 8) * N + c0) =
                        __floats2half2_rn(acc[i][j][2], acc[i][j][3]);
            }
        }
    } else {                    // xr / sk -> fp32
        float* C = (blockIdx.z == 1) ? C1 : C2;
#pragma unroll
        for (int i = 0; i < 2; i++) {
#pragma unroll
            for (int j = 0; j < JN; j++) {
                int r0 = blockRow + wm + i * 16 + (lane >> 2);
                int c0 = blockCol + wn + j * 8 + (lane & 3) * 2;
                if (r0 < M) {
                    float2 v = make_float2(acc[i][j][0], acc[i][j][1]);
                    *(float2*)(C + (size_t)r0 * N + c0) = v;
                }
                if (r0 + 8 < M) {
                    float2 v = make_float2(acc[i][j][2], acc[i][j][3]);
                    *(float2*)(C + (size_t)(r0 + 8) * N + c0) = v;
                }
            }
        }
    }
}

#define GEMM_SMEM(BNv) (3 * (BM * APH + (BNv) * APH) * 2)

// ---------------- fused edge phase: score + online softmax + aggregate ------
// xl is fp16 (halved gather traffic). xr/sk/biases fp32. Accumulation fp32.
template <int NK4>   // 4-elem chunks per lane; D = NK4*128
__global__ void gat_edge_fused_kernel(const __half* __restrict__ xl,
                                      const float* __restrict__ xr,
                                      const float* __restrict__ att,
                                      const float* __restrict__ sk,
                                      const float* __restrict__ bc,
                                      const float* __restrict__ bs,
                                      float* __restrict__ out,
                                      __half* __restrict__ outh,
                                      int doRelu) {
    const int D = NK4 * 128;
    int v = (blockIdx.x * blockDim.x + threadIdx.x) >> 5;
    if (v >= N_NODES) return;
    int lane = threadIdx.x & 31;
    int beg = g_rowptr[v], end = g_rowptr[v + 1];

    const float4* xr4  = (const float4*)(xr + (size_t)v * D);
    const float4* att4 = (const float4*)att;
    float4 xrv[NK4], atv[NK4], acc[NK4];
#pragma unroll
    for (int k = 0; k < NK4; k++) {
        xrv[k] = xr4[lane + 32 * k];
        atv[k] = att4[lane + 32 * k];
        acc[k] = make_float4(0.f, 0.f, 0.f, 0.f);
    }

    float m = -INFINITY, ssum = 0.f;
    for (int i = beg; i < end; i++) {
        int s = g_srcs[i];   // uniform across warp
        const uint2* xs = (const uint2*)(xl + (size_t)s * D);
        float4 vx[NK4];
#pragma unroll
        for (int k = 0; k < NK4; k++) {
            uint2 raw = xs[lane + 32 * k];          // 4 halves, 8B coalesced
            float2 f01 = __half22float2(*(__half2*)&raw.x);
            float2 f23 = __half22float2(*(__half2*)&raw.y);
            vx[k] = make_float4(f01.x, f01.y, f23.x, f23.y);
        }

        float sc = 0.f;
#pragma unroll
        for (int k = 0; k < NK4; k++) {
            float t;
            t = vx[k].x + xrv[k].x; sc = fmaf((t > 0.f ? t : 0.2f * t), atv[k].x, sc);
            t = vx[k].y + xrv[k].y; sc = fmaf((t > 0.f ? t : 0.2f * t), atv[k].y, sc);
            t = vx[k].z + xrv[k].z; sc = fmaf((t > 0.f ? t : 0.2f * t), atv[k].z, sc);
            t = vx[k].w + xrv[k].w; sc = fmaf((t > 0.f ? t : 0.2f * t), atv[k].w, sc);
        }
#pragma unroll
        for (int off = 16; off > 0; off >>= 1)
            sc += __shfl_xor_sync(0xFFFFFFFFu, sc, off);

        float mn = fmaxf(m, sc);
        float scale = __expf(m - mn);   // first iter: exp(-inf)=0
        float w = __expf(sc - mn);
        ssum = ssum * scale + w;
#pragma unroll
        for (int k = 0; k < NK4; k++) {
            acc[k].x = fmaf(acc[k].x, scale, w * vx[k].x);
            acc[k].y = fmaf(acc[k].y, scale, w * vx[k].y);
            acc[k].z = fmaf(acc[k].z, scale, w * vx[k].z);
            acc[k].w = fmaf(acc[k].w, scale, w * vx[k].w);
        }
        m = mn;
    }

    float inv = 1.f / (ssum + 1e-16f);
    const float4* bc4 = (const float4*)bc;
    const float4* bs4 = (const float4*)bs;
    const float4* sk4 = (const float4*)(sk + (size_t)v * D);
#pragma unroll
    for (int k = 0; k < NK4; k++) {
        int idx = lane + 32 * k;
        float4 vbc = bc4[idx], vbs = bs4[idx], vsk = sk4[idx];
        float4 o;
        o.x = fmaf(acc[k].x, inv, vbc.x + vbs.x + vsk.x);
        o.y = fmaf(acc[k].y, inv, vbc.y + vbs.y + vsk.y);
        o.z = fmaf(acc[k].z, inv, vbc.z + vbs.z + vsk.z);
        o.w = fmaf(acc[k].w, inv, vbc.w + vbs.w + vsk.w);
        if (doRelu) {
            o.x = fmaxf(o.x, 0.f); o.y = fmaxf(o.y, 0.f);
            o.z = fmaxf(o.z, 0.f); o.w = fmaxf(o.w, 0.f);
        }
        if (outh) {
            __half2* oh = (__half2*)(outh + (size_t)v * D) + idx * 2;
            oh[0] = __floats2half2_rn(o.x, o.y);
            oh[1] = __floats2half2_rn(o.z, o.w);
        } else {
            ((float4*)(out + (size_t)v * D))[idx] = o;
        }
    }
}

// ---------------- host-side orchestration -----------------------------------
static void run_layer(const __half* A, int K, int D,
                      const __half* Wt_l, const __half* Wt_r, const __half* Wt_s,
                      const float* att, const float* bc, const float* bs,
                      float* out, __half* outh, int doRelu,
                      __half* xlh, float* xr, float* sk) {
    if (D >= 256) {
        dim3 gg(D / 128, (N_NODES + BM - 1) / BM, 3);
        gemm_f16_b3_kernel<128, 8><<<gg, 256, GEMM_SMEM(128)>>>(
            A, Wt_l, Wt_r, Wt_s, xlh, xr, sk, N_NODES, D, K);
    } else {
        dim3 gg(D / 64, (N_NODES + BM - 1) / BM, 3);
        gemm_f16_b3_kernel<64, 4><<<gg, 256, GEMM_SMEM(64)>>>(
            A, Wt_l, Wt_r, Wt_s, xlh, xr, sk, N_NODES, D, K);
    }

    int warpsPerBlock = 8;
    int nbv = (N_NODES + warpsPerBlock - 1) / warpsPerBlock;
    if (D == 512)
        gat_edge_fused_kernel<4><<<nbv, warpsPerBlock * 32>>>(xlh, xr, att, sk, bc, bs, out, outh, doRelu);
    else if (D == 256)
        gat_edge_fused_kernel<2><<<nbv, warpsPerBlock * 32>>>(xlh, xr, att, sk, bc, bs, out, outh, doRelu);
    else
        gat_edge_fused_kernel<1><<<nbv, warpsPerBlock * 32>>>(xlh, xr, att, sk, bc, bs, out, outh, doRelu);
}

extern "C" void kernel_launch(void* const* d_in, const int* in_sizes, int n_in,
                              void* d_out, int out_size) {
    const float* x  = (const float*)d_in[0];
    const int*   ei = (const int*)d_in[1];
    const int* src = ei;
    const int* dst = ei + N_EDGES;

    const float* Wl[3]  = {(const float*)d_in[2],  (const float*)d_in[8],  (const float*)d_in[14]};
    const float* Wr[3]  = {(const float*)d_in[3],  (const float*)d_in[9],  (const float*)d_in[15]};
    const float* att[3] = {(const float*)d_in[4],  (const float*)d_in[10], (const float*)d_in[16]};
    const float* bc[3]  = {(const float*)d_in[5],  (const float*)d_in[11], (const float*)d_in[17]};
    const float* Ws[3]  = {(const float*)d_in[6],  (const float*)d_in[12], (const float*)d_in[18]};
    const float* bs[3]  = {(const float*)d_in[7],  (const float*)d_in[13], (const float*)d_in[19]};

    float *xr, *sk;
    __half *xlh, *h1h, *h2h, *xah, *wth;
    cudaGetSymbolAddress((void**)&xlh, g_xlh);
    cudaGetSymbolAddress((void**)&xr,  g_xr);
    cudaGetSymbolAddress((void**)&sk,  g_sk);
    cudaGetSymbolAddress((void**)&h1h, g_h1h);
    cudaGetSymbolAddress((void**)&h2h, g_h2h);
    cudaGetSymbolAddress((void**)&xah, g_xah);
    cudaGetSymbolAddress((void**)&wth, g_wth);

    (void)cudaFuncSetAttribute(gemm_f16_b3_kernel<128, 8>,
                               cudaFuncAttributeMaxDynamicSharedMemorySize, GEMM_SMEM(128));
    (void)cudaFuncSetAttribute(gemm_f16_b3_kernel<64, 4>,
                               cudaFuncAttributeMaxDynamicSharedMemorySize, GEMM_SMEM(64));

    // merged prepass (one launch): transpose+fp16 weights, fp16 x, zero counts
    int wK[9] = {256, 256, 256, 512, 512, 512, 256, 256, 256};
    int wN[9] = {512, 512, 512, 256, 256, 256, 128, 128, 128};
    const float* wsrc[9] = {Wl[0], Wr[0], Ws[0], Wl[1], Wr[1], Ws[1], Wl[2], Wr[2], Ws[2]};
    __half* wdst[9];
    {
        int off = 0;
        for (int i = 0; i < 9; i++) { wdst[i] = wth + off; off += wK[i] * wN[i]; }
    }
    PrepArgs pa;
    for (int i = 0; i < 9; i++) {
        pa.wsrc[i] = wsrc[i]; pa.wdst[i] = wdst[i];
        pa.K[i] = wK[i]; pa.N[i] = wN[i];
    }
    pa.xsrc = x; pa.xdst = xah; pa.xn4 = N_NODES * 256 / 4;
    prep_kernel<<<dim3(160, 11), 256>>>(pa);

    // CSR build (counting sort of edges by dst)
    hist_kernel<<<(N_EDGES + 255) / 256, 256>>>(dst);
    scan_kernel<<<1, 1024>>>();
    scatter_kernel<<<(N_EDGES + 255) / 256, 256>>>(src, dst);

    // Layer 1: 256 -> 512, relu, fp16 out for next GEMM
    run_layer(xah, 256, 512, wdst[0], wdst[1], wdst[2], att[0], bc[0], bs[0],
              nullptr, h1h, 1, xlh, xr, sk);
    // Layer 2: 512 -> 256, relu, fp16 out
    run_layer(h1h, 512, 256, wdst[3], wdst[4], wdst[5], att[1], bc[1], bs[1],
              nullptr, h2h, 1, xlh, xr, sk);
    // Layer 3: 256 -> 128, no relu, fp32 output
    run_layer(h2h, 256, 128, wdst[6], wdst[7], wdst[8], att[2], bc[2], bs[2],
              (float*)d_out, nullptr, 0, xlh, xr, sk);
}

// round 14
// speedup vs baseline: 1.4969x; 1.0597x over previous
#include <cuda_runtime.h>
#include <cuda_fp16.h>
#include <cstdint>
#include <stdint.h>
#include <math.h>

#define N_NODES 20000
#define N_EDGES 320000
#define DMAX    512

// ---------------- scratch (static device globals; no allocation allowed) ----
__device__ __align__(16) __half g_xlh[N_NODES * DMAX];  // fp16 xl (edge-gather operand)
__device__ __align__(16) float  g_xr[N_NODES * DMAX];
__device__ __align__(16) float  g_sk[N_NODES * DMAX];
__device__ __align__(16) __half g_h1h[N_NODES * 512];   // fp16 activations (GEMM A input)
__device__ __align__(16) __half g_h2h[N_NODES * 256];
__device__ __align__(16) __half g_xah[N_NODES * 256];   // fp16 copy of x
__device__ __align__(16) __half g_wth[900000];          // fp16 transposed weights [N][K]
__device__ __align__(16) int    g_srcs [N_EDGES];
__device__ __align__(16) int    g_count [N_NODES];
__device__ __align__(16) int    g_cursor[N_NODES];
__device__ __align__(16) int    g_rowptr[N_NODES + 4];

__device__ __forceinline__ uint32_t smem_u32(const void* p) {
    return (uint32_t)__cvta_generic_to_shared(p);
}

// ------- merged prepass: transpose+fp16 9 weights, fp16 x, zero counts ------
struct PrepArgs {
    const float* wsrc[9];
    __half*      wdst[9];
    int          K[9], N[9];
    const float* xsrc;
    __half*      xdst;
    int          xn4;
};

__global__ void prep_kernel(PrepArgs pa) {
    int s = blockIdx.y;
    if (s == 9) {   // x -> fp16
        const float4* in = (const float4*)pa.xsrc;
        for (int i = blockIdx.x * blockDim.x + threadIdx.x; i < pa.xn4;
             i += gridDim.x * blockDim.x) {
            float4 v = in[i];
            __half2* o = (__half2*)(pa.xdst + (size_t)i * 4);
            o[0] = __floats2half2_rn(v.x, v.y);
            o[1] = __floats2half2_rn(v.z, v.w);
        }
        return;
    }
    if (s == 10) {  // zero count/cursor
        int4 z = make_int4(0, 0, 0, 0);
        for (int i = blockIdx.x * blockDim.x + threadIdx.x; i < N_NODES / 4;
             i += gridDim.x * blockDim.x) {
            ((int4*)g_count)[i]  = z;
            ((int4*)g_cursor)[i] = z;
        }
        return;
    }
    // transpose + convert: Wt[n][k] = fp16(W[k][n])
    int K = pa.K[s], N = pa.N[s];
    const float* src = pa.wsrc[s];
    __half*      dst = pa.wdst[s];
    int tpn = N / 32, tpk = K / 32, nt = tpn * tpk;
    __shared__ float tile[32][33];
    int tx = threadIdx.x & 31, ty = threadIdx.x >> 5;   // 32x8
    for (int t = blockIdx.x; t < nt; t += gridDim.x) {
        int n0 = (t % tpn) * 32, k0 = (t / tpn) * 32;
#pragma unroll
        for (int i = 0; i < 4; i++)
            tile[ty + 8 * i][tx] = src[(size_t)(k0 + ty + 8 * i) * N + n0 + tx];
        __syncthreads();
#pragma unroll
        for (int i = 0; i < 4; i++)
            dst[(size_t)(n0 + ty + 8 * i) * K + k0 + tx] = __float2half(tile[tx][ty + 8 * i]);
        __syncthreads();
    }
}

// ---------------- CSR build (counting sort by dst) --------------------------
__global__ void hist_kernel(const int* __restrict__ dst) {
    int e = blockIdx.x * blockDim.x + threadIdx.x;
    if (e < N_EDGES) atomicAdd(&g_count[dst[e]], 1);
}

__global__ void scan_kernel() {
    const int CH = 20;
    int tid = threadIdx.x;
    int lane = tid & 31, w = tid >> 5;
    int beg = tid * CH;
    int vals[CH];
    int sum = 0;
    if (beg < N_NODES) {
        const int4* p = (const int4*)(g_count + beg);
#pragma unroll
        for (int i = 0; i < CH / 4; i++) {
            int4 v = p[i];
            vals[i * 4 + 0] = v.x; vals[i * 4 + 1] = v.y;
            vals[i * 4 + 2] = v.z; vals[i * 4 + 3] = v.w;
            sum += v.x + v.y + v.z + v.w;
        }
    }
    int inc = sum;
#pragma unroll
    for (int off = 1; off < 32; off <<= 1) {
        int t = __shfl_up_sync(0xFFFFFFFFu, inc, off);
        if (lane >= off) inc += t;
    }
    __shared__ int wsum[32];
    if (lane == 31) wsum[w] = inc;
    __syncthreads();
    if (w == 0) {
        int v = wsum[lane];
#pragma unroll
        for (int off = 1; off < 32; off <<= 1) {
            int t = __shfl_up_sync(0xFFFFFFFFu, v, off);
            if (lane >= off) v += t;
        }
        wsum[lane] = v;
    }
    __syncthreads();
    int base = (w > 0 ? wsum[w - 1] : 0) + inc - sum;
    if (beg < N_NODES) {
        int run = base;
        int4* rp = (int4*)(g_rowptr + beg);
#pragma unroll
        for (int i = 0; i < CH / 4; i++) {
            int4 o;
            o.x = run; run += vals[i * 4 + 0];
            o.y = run; run += vals[i * 4 + 1];
            o.z = run; run += vals[i * 4 + 2];
            o.w = run; run += vals[i * 4 + 3];
            rp[i] = o;
        }
    }
    if (tid == 0) g_rowptr[N_NODES] = wsum[31];
}

__global__ void scatter_kernel(const int* __restrict__ src, const int* __restrict__ dst) {
    int e = blockIdx.x * blockDim.x + threadIdx.x;
    if (e < N_EDGES) {
        int d = dst[e];
        int pos = g_rowptr[d] + atomicAdd(&g_cursor[d], 1);
        g_srcs[pos] = src[e];
    }
}

// ---------------- FP16 mma.sync GEMM (z-batched over 3 weight mats) ---------
// C = A @ W.  A fp16 row-major; W pre-transposed fp16 [N][K].
// z=0 writes fp16 (xl); z=1,2 write fp32 (xr, sk).
// CTA tile 128 x BNv x 32, 8 warps (4m x 2n), mma.m16n8k16.f16 (fp32 accum).
// Fragments loaded via ldmatrix.x4 (12 LDSM vs 48 LDS per k-tile).
#define BM 128
#define GBK 32
#define APH 40

__device__ __forceinline__ void cpasync16(void* smem, const void* g, int sz) {
    uint32_t sa = (uint32_t)__cvta_generic_to_shared(smem);
    asm volatile("cp.async.cg.shared.global [%0], [%1], 16, %2;\n"
                 :: "r"(sa), "l"(g), "r"(sz));
}

__device__ __forceinline__ void ldsm_x4(uint32_t& r0, uint32_t& r1,
                                        uint32_t& r2, uint32_t& r3, uint32_t addr) {
    asm volatile("ldmatrix.sync.aligned.m8n8.x4.shared.b16 {%0,%1,%2,%3}, [%4];"
                 : "=r"(r0), "=r"(r1), "=r"(r2), "=r"(r3) : "r"(addr));
}

template <int BNv, int JN>      // JN = BNv/16 (j-tiles of 8 per warp); JN even
__global__ __launch_bounds__(256, 2)
void gemm_f16_b3_kernel(const __half* __restrict__ A,
                        const __half* __restrict__ W0, const __half* __restrict__ W1,
                        const __half* __restrict__ W2,
                        __half* __restrict__ C0h, float* __restrict__ C1,
                        float* __restrict__ C2,
                        int M, int N, int K) {
    const __half* Wt = (blockIdx.z == 0) ? W0 : (blockIdx.z == 1) ? W1 : W2;

    extern __shared__ __half smemH[];
    __half (*As)[BM][APH]  = (__half (*)[BM][APH])smemH;
    __half (*Bs)[BNv][APH] = (__half (*)[BNv][APH])(smemH + 3 * BM * APH);

    int tid  = threadIdx.x;
    int warp = tid >> 5;
    int lane = tid & 31;
    int blockRow = blockIdx.y * BM;
    int blockCol = blockIdx.x * BNv;
    int wm = (warp >> 1) * 32;
    int wn = (warp & 1) * (JN * 8);

    float acc[2][JN][4];
#pragma unroll
    for (int i = 0; i < 2; i++)
#pragma unroll
        for (int j = 0; j < JN; j++)
#pragma unroll
            for (int t = 0; t < 4; t++) acc[i][j][t] = 0.f;

    auto loadStage = [&](int s, int k0) {
#pragma unroll
        for (int j = 0; j < 2; j++) {
            int c = tid + j * 256;
            int row = c >> 2, part = c & 3;
            int gRow = blockRow + row;
            int ok = (gRow < M);
            const __half* gp = A + (size_t)(ok ? gRow : 0) * K + k0 + part * 8;
            cpasync16(&As[s][row][part * 8], gp, ok ? 16 : 0);
        }
#pragma unroll
        for (int j = 0; j < BNv / 64; j++) {
            int c = tid + j * 256;
            int row = c >> 2, part = c & 3;
            const __half* gp = Wt + (size_t)(blockCol + row) * K + k0 + part * 8;
            cpasync16(&Bs[s][row][part * 8], gp, 16);
        }
        asm volatile("cp.async.commit_group;\n");
    };

    // per-lane ldmatrix address components (within a stage)
    int aRow = wm + (lane & 15);            // + i*16
    int aCol = (lane >> 4) * 8;             // + ks*16
    int bRow = wn + ((lane >> 4) << 3) + (lane & 7);   // + j*8 (pair base)
    int bCol = ((lane >> 3) & 1) * 8;       // + ks*16

    int nK = K / GBK;
    loadStage(0, 0);
    loadStage(1, GBK);

    for (int kt = 0; kt < nK; kt++) {
        int s = kt % 3;
        if (kt + 2 < nK) {
            loadStage((kt + 2) % 3, (kt + 2) * GBK);
            asm volatile("cp.async.wait_group 2;\n");
        } else if (kt + 1 < nK) {
            asm volatile("cp.async.wait_group 1;\n");
        } else {
            asm volatile("cp.async.wait_group 0;\n");
        }
        __syncthreads();

#pragma unroll
        for (int ks = 0; ks < 2; ks++) {
            uint32_t aF[2][4];
#pragma unroll
            for (int i = 0; i < 2; i++) {
                uint32_t ad = smem_u32(&As[s][aRow + i * 16][aCol + ks * 16]);
                ldsm_x4(aF[i][0], aF[i][1], aF[i][2], aF[i][3], ad);
            }
            uint32_t bF[JN][2];
#pragma unroll
            for (int j = 0; j < JN; j += 2) {
                uint32_t bd = smem_u32(&Bs[s][bRow + j * 8][bCol + ks * 16]);
                ldsm_x4(bF[j][0], bF[j][1], bF[j + 1][0], bF[j + 1][1], bd);
            }
#pragma unroll
            for (int i = 0; i < 2; i++)
#pragma unroll
                for (int j = 0; j < JN; j++) {
                    asm volatile(
                        "mma.sync.aligned.m16n8k16.row.col.f32.f16.f16.f32 "
                        "{%0,%1,%2,%3}, {%4,%5,%6,%7}, {%8,%9}, {%0,%1,%2,%3};\n"
                        : "+f"(acc[i][j][0]), "+f"(acc[i][j][1]),
                          "+f"(acc[i][j][2]), "+f"(acc[i][j][3])
                        : "r"(aF[i][0]), "r"(aF[i][1]), "r"(aF[i][2]), "r"(aF[i][3]),
                          "r"(bF[j][0]), "r"(bF[j][1]));
                }
        }
        __syncthreads();
    }

    if (blockIdx.z == 0) {      // xl -> fp16
#pragma unroll
        for (int i = 0; i < 2; i++) {
#pragma unroll
            for (int j = 0; j < JN; j++) {
                int r0 = blockRow + wm + i * 16 + (lane >> 2);
                int c0 = blockCol + wn + j * 8 + (lane & 3) * 2;
                if (r0 < M)
                    *(__half2*)(C0h + (size_t)r0 * N + c0) =
                        __floats2half2_rn(acc[i][j][0], acc[i][j][1]);
                if (r0 + 8 < M)
                    *(__half2*)(C0h + (size_t)(r0 + 8) * N + c0) =
                        __floats2half2_rn(acc[i][j][2], acc[i][j][3]);
            }
        }
    } else {                    // xr / sk -> fp32
        float* C = (blockIdx.z == 1) ? C1 : C2;
#pragma unroll
        for (int i = 0; i < 2; i++) {
#pragma unroll
            for (int j = 0; j < JN; j++) {
                int r0 = blockRow + wm + i * 16 + (lane >> 2);
                int c0 = blockCol + wn + j * 8 + (lane & 3) * 2;
                if (r0 < M) {
                    float2 v = make_float2(acc[i][j][0], acc[i][j][1]);
                    *(float2*)(C + (size_t)r0 * N + c0) = v;
                }
                if (r0 + 8 < M) {
                    float2 v = make_float2(acc[i][j][2], acc[i][j][3]);
                    *(float2*)(C + (size_t)(r0 + 8) * N + c0) = v;
                }
            }
        }
    }
}

#define GEMM_SMEM(BNv) (3 * (BM * APH + (BNv) * APH) * 2)

// ---------------- fused edge phase: score + online softmax + aggregate ------
// xl is fp16. xr/sk/biases fp32. Accumulation fp32.
template <int NK4>   // 4-elem chunks per lane; D = NK4*128
__global__ void gat_edge_fused_kernel(const __half* __restrict__ xl,
                                      const float* __restrict__ xr,
                                      const float* __restrict__ att,
                                      const float* __restrict__ sk,
                                      const float* __restrict__ bc,
                                      const float* __restrict__ bs,
                                      float* __restrict__ out,
                                      __half* __restrict__ outh,
                                      int doRelu) {
    const int D = NK4 * 128;
    int v = (blockIdx.x * blockDim.x + threadIdx.x) >> 5;
    if (v >= N_NODES) return;
    int lane = threadIdx.x & 31;
    int beg = g_rowptr[v], end = g_rowptr[v + 1];

    const float4* xr4  = (const float4*)(xr + (size_t)v * D);
    const float4* att4 = (const float4*)att;
    float4 xrv[NK4], atv[NK4], acc[NK4];
#pragma unroll
    for (int k = 0; k < NK4; k++) {
        xrv[k] = xr4[lane + 32 * k];
        atv[k] = att4[lane + 32 * k];
        acc[k] = make_float4(0.f, 0.f, 0.f, 0.f);
    }

    float m = -INFINITY, ssum = 0.f;
    for (int i = beg; i < end; i++) {
        int s = g_srcs[i];   // uniform across warp
        const uint2* xs = (const uint2*)(xl + (size_t)s * D);
        float4 vx[NK4];
#pragma unroll
        for (int k = 0; k < NK4; k++) {
            uint2 raw = xs[lane + 32 * k];          // 4 halves, 8B coalesced
            float2 f01 = __half22float2(*(__half2*)&raw.x);
            float2 f23 = __half22float2(*(__half2*)&raw.y);
            vx[k] = make_float4(f01.x, f01.y, f23.x, f23.y);
        }

        float sc = 0.f;
#pragma unroll
        for (int k = 0; k < NK4; k++) {
            float t;
            t = vx[k].x + xrv[k].x; sc = fmaf((t > 0.f ? t : 0.2f * t), atv[k].x, sc);
            t = vx[k].y + xrv[k].y; sc = fmaf((t > 0.f ? t : 0.2f * t), atv[k].y, sc);
            t = vx[k].z + xrv[k].z; sc = fmaf((t > 0.f ? t : 0.2f * t), atv[k].z, sc);
            t = vx[k].w + xrv[k].w; sc = fmaf((t > 0.f ? t : 0.2f * t), atv[k].w, sc);
        }
#pragma unroll
        for (int off = 16; off > 0; off >>= 1)
            sc += __shfl_xor_sync(0xFFFFFFFFu, sc, off);

        float mn = fmaxf(m, sc);
        float scale = __expf(m - mn);   // first iter: exp(-inf)=0
        float w = __expf(sc - mn);
        ssum = ssum * scale + w;
#pragma unroll
        for (int k = 0; k < NK4; k++) {
            acc[k].x = fmaf(acc[k].x, scale, w * vx[k].x);
            acc[k].y = fmaf(acc[k].y, scale, w * vx[k].y);
            acc[k].z = fmaf(acc[k].z, scale, w * vx[k].z);
            acc[k].w = fmaf(acc[k].w, scale, w * vx[k].w);
        }
        m = mn;
    }

    float inv = 1.f / (ssum + 1e-16f);
    const float4* bc4 = (const float4*)bc;
    const float4* bs4 = (const float4*)bs;
    const float4* sk4 = (const float4*)(sk + (size_t)v * D);
#pragma unroll
    for (int k = 0; k < NK4; k++) {
        int idx = lane + 32 * k;
        float4 vbc = bc4[idx], vbs = bs4[idx], vsk = sk4[idx];
        float4 o;
        o.x = fmaf(acc[k].x, inv, vbc.x + vbs.x + vsk.x);
        o.y = fmaf(acc[k].y, inv, vbc.y + vbs.y + vsk.y);
        o.z = fmaf(acc[k].z, inv, vbc.z + vbs.z + vsk.z);
        o.w = fmaf(acc[k].w, inv, vbc.w + vbs.w + vsk.w);
        if (doRelu) {
            o.x = fmaxf(o.x, 0.f); o.y = fmaxf(o.y, 0.f);
            o.z = fmaxf(o.z, 0.f); o.w = fmaxf(o.w, 0.f);
        }
        if (outh) {
            __half2* oh = (__half2*)(outh + (size_t)v * D) + idx * 2;
            oh[0] = __floats2half2_rn(o.x, o.y);
            oh[1] = __floats2half2_rn(o.z, o.w);
        } else {
            ((float4*)(out + (size_t)v * D))[idx] = o;
        }
    }
}

// ---------------- host-side orchestration -----------------------------------
static void run_layer(const __half* A, int K, int D,
                      const __half* Wt_l, const __half* Wt_r, const __half* Wt_s,
                      const float* att, const float* bc, const float* bs,
                      float* out, __half* outh, int doRelu,
                      __half* xlh, float* xr, float* sk) {
    if (D >= 256) {
        dim3 gg(D / 128, (N_NODES + BM - 1) / BM, 3);
        gemm_f16_b3_kernel<128, 8><<<gg, 256, GEMM_SMEM(128)>>>(
            A, Wt_l, Wt_r, Wt_s, xlh, xr, sk, N_NODES, D, K);
    } else {
        dim3 gg(D / 64, (N_NODES + BM - 1) / BM, 3);
        gemm_f16_b3_kernel<64, 4><<<gg, 256, GEMM_SMEM(64)>>>(
            A, Wt_l, Wt_r, Wt_s, xlh, xr, sk, N_NODES, D, K);
    }

    int warpsPerBlock = 8;
    int nbv = (N_NODES + warpsPerBlock - 1) / warpsPerBlock;
    if (D == 512)
        gat_edge_fused_kernel<4><<<nbv, warpsPerBlock * 32>>>(xlh, xr, att, sk, bc, bs, out, outh, doRelu);
    else if (D == 256)
        gat_edge_fused_kernel<2><<<nbv, warpsPerBlock * 32>>>(xlh, xr, att, sk, bc, bs, out, outh, doRelu);
    else
        gat_edge_fused_kernel<1><<<nbv, warpsPerBlock * 32>>>(xlh, xr, att, sk, bc, bs, out, outh, doRelu);
}

extern "C" void kernel_launch(void* const* d_in, const int* in_sizes, int n_in,
                              void* d_out, int out_size) {
    const float* x  = (const float*)d_in[0];
    const int*   ei = (const int*)d_in[1];
    const int* src = ei;
    const int* dst = ei + N_EDGES;

    const float* Wl[3]  = {(const float*)d_in[2],  (const float*)d_in[8],  (const float*)d_in[14]};
    const float* Wr[3]  = {(const float*)d_in[3],  (const float*)d_in[9],  (const float*)d_in[15]};
    const float* att[3] = {(const float*)d_in[4],  (const float*)d_in[10], (const float*)d_in[16]};
    const float* bc[3]  = {(const float*)d_in[5],  (const float*)d_in[11], (const float*)d_in[17]};
    const float* Ws[3]  = {(const float*)d_in[6],  (const float*)d_in[12], (const float*)d_in[18]};
    const float* bs[3]  = {(const float*)d_in[7],  (const float*)d_in[13], (const float*)d_in[19]};

    float *xr, *sk;
    __half *xlh, *h1h, *h2h, *xah, *wth;
    cudaGetSymbolAddress((void**)&xlh, g_xlh);
    cudaGetSymbolAddress((void**)&xr,  g_xr);
    cudaGetSymbolAddress((void**)&sk,  g_sk);
    cudaGetSymbolAddress((void**)&h1h, g_h1h);
    cudaGetSymbolAddress((void**)&h2h, g_h2h);
    cudaGetSymbolAddress((void**)&xah, g_xah);
    cudaGetSymbolAddress((void**)&wth, g_wth);

    (void)cudaFuncSetAttribute(gemm_f16_b3_kernel<128, 8>,
                               cudaFuncAttributeMaxDynamicSharedMemorySize, GEMM_SMEM(128));
    (void)cudaFuncSetAttribute(gemm_f16_b3_kernel<64, 4>,
                               cudaFuncAttributeMaxDynamicSharedMemorySize, GEMM_SMEM(64));

    // merged prepass (one launch): transpose+fp16 weights, fp16 x, zero counts
    int wK[9] = {256, 256, 256, 512, 512, 512, 256, 256, 256};
    int wN[9] = {512, 512, 512, 256, 256, 256, 128, 128, 128};
    const float* wsrc[9] = {Wl[0], Wr[0], Ws[0], Wl[1], Wr[1], Ws[1], Wl[2], Wr[2], Ws[2]};
    __half* wdst[9];
    {
        int off = 0;
        for (int i = 0; i < 9; i++) { wdst[i] = wth + off; off += wK[i] * wN[i]; }
    }
    PrepArgs pa;
    for (int i = 0; i < 9; i++) {
        pa.wsrc[i] = wsrc[i]; pa.wdst[i] = wdst[i];
        pa.K[i] = wK[i]; pa.N[i] = wN[i];
    }
    pa.xsrc = x; pa.xdst = xah; pa.xn4 = N_NODES * 256 / 4;
    prep_kernel<<<dim3(160, 11), 256>>>(pa);

    // CSR build (counting sort of edges by dst)
    hist_kernel<<<(N_EDGES + 255) / 256, 256>>>(dst);
    scan_kernel<<<1, 1024>>>();
    scatter_kernel<<<(N_EDGES + 255) / 256, 256>>>(src, dst);

    // Layer 1: 256 -> 512, relu, fp16 out for next GEMM
    run_layer(xah, 256, 512, wdst[0], wdst[1], wdst[2], att[0], bc[0], bs[0],
              nullptr, h1h, 1, xlh, xr, sk);
    // Layer 2: 512 -> 256, relu, fp16 out
    run_layer(h1h, 512, 256, wdst[3], wdst[4], wdst[5], att[1], bc[1], bs[1],
              nullptr, h2h, 1, xlh, xr, sk);
    // Layer 3: 256 -> 128, no relu, fp32 output
    run_layer(h2h, 256, 128, wdst[6], wdst[7], wdst[8], att[2], bc[2], bs[2],
              (float*)d_out, nullptr, 0, xlh, xr, sk);
}

// round 15
// speedup vs baseline: 1.5548x; 1.0387x over previous
#include <cuda_runtime.h>
#include <cuda_fp16.h>
#include <cstdint>
#include <stdint.h>
#include <math.h>

#define N_NODES 20000
#define N_EDGES 320000
#define DMAX    512

// ---------------- scratch (static device globals; no allocation allowed) ----
__device__ __align__(16) __half g_xlh[N_NODES * DMAX];  // fp16 xl (edge-gather operand)
__device__ __align__(16) float  g_xr[N_NODES * DMAX];
__device__ __align__(16) float  g_sk[N_NODES * DMAX];
__device__ __align__(16) __half g_h1h[N_NODES * 512];   // fp16 activations (GEMM A input)
__device__ __align__(16) __half g_h2h[N_NODES * 256];
__device__ __align__(16) __half g_xah[N_NODES * 256];   // fp16 copy of x
__device__ __align__(16) __half g_wth[900000];          // fp16 transposed weights [N][K]
__device__ __align__(16) int    g_srcs [N_EDGES];
__device__ __align__(16) int    g_count [N_NODES];
__device__ __align__(16) int    g_cursor[N_NODES];
__device__ __align__(16) int    g_rowptr[N_NODES + 4];

__device__ __forceinline__ uint32_t smem_u32(const void* p) {
    return (uint32_t)__cvta_generic_to_shared(p);
}

// ------- merged prepass: transpose+fp16 9 weights, fp16 x, zero counts ------
struct PrepArgs {
    const float* wsrc[9];
    __half*      wdst[9];
    int          K[9], N[9];
    const float* xsrc;
    __half*      xdst;
    int          xn4;
};

__global__ void prep_kernel(PrepArgs pa) {
    int s = blockIdx.y;
    if (s == 9) {   // x -> fp16
        const float4* in = (const float4*)pa.xsrc;
        for (int i = blockIdx.x * blockDim.x + threadIdx.x; i < pa.xn4;
             i += gridDim.x * blockDim.x) {
            float4 v = in[i];
            __half2* o = (__half2*)(pa.xdst + (size_t)i * 4);
            o[0] = __floats2half2_rn(v.x, v.y);
            o[1] = __floats2half2_rn(v.z, v.w);
        }
        return;
    }
    if (s == 10) {  // zero count/cursor
        int4 z = make_int4(0, 0, 0, 0);
        for (int i = blockIdx.x * blockDim.x + threadIdx.x; i < N_NODES / 4;
             i += gridDim.x * blockDim.x) {
            ((int4*)g_count)[i]  = z;
            ((int4*)g_cursor)[i] = z;
        }
        return;
    }
    // transpose + convert: Wt[n][k] = fp16(W[k][n])
    int K = pa.K[s], N = pa.N[s];
    const float* src = pa.wsrc[s];
    __half*      dst = pa.wdst[s];
    int tpn = N / 32, tpk = K / 32, nt = tpn * tpk;
    __shared__ float tile[32][33];
    int tx = threadIdx.x & 31, ty = threadIdx.x >> 5;   // 32x8
    for (int t = blockIdx.x; t < nt; t += gridDim.x) {
        int n0 = (t % tpn) * 32, k0 = (t / tpn) * 32;
#pragma unroll
        for (int i = 0; i < 4; i++)
            tile[ty + 8 * i][tx] = src[(size_t)(k0 + ty + 8 * i) * N + n0 + tx];
        __syncthreads();
#pragma unroll
        for (int i = 0; i < 4; i++)
            dst[(size_t)(n0 + ty + 8 * i) * K + k0 + tx] = __float2half(tile[tx][ty + 8 * i]);
        __syncthreads();
    }
}

// ---------------- CSR build (counting sort by dst) --------------------------
__global__ void hist_kernel(const int* __restrict__ dst) {
    int e = blockIdx.x * blockDim.x + threadIdx.x;
    if (e < N_EDGES) atomicAdd(&g_count[dst[e]], 1);
}

__global__ void scan_kernel() {
    const int CH = 20;
    int tid = threadIdx.x;
    int lane = tid & 31, w = tid >> 5;
    int beg = tid * CH;
    int vals[CH];
    int sum = 0;
    if (beg < N_NODES) {
        const int4* p = (const int4*)(g_count + beg);
#pragma unroll
        for (int i = 0; i < CH / 4; i++) {
            int4 v = p[i];
            vals[i * 4 + 0] = v.x; vals[i * 4 + 1] = v.y;
            vals[i * 4 + 2] = v.z; vals[i * 4 + 3] = v.w;
            sum += v.x + v.y + v.z + v.w;
        }
    }
    int inc = sum;
#pragma unroll
    for (int off = 1; off < 32; off <<= 1) {
        int t = __shfl_up_sync(0xFFFFFFFFu, inc, off);
        if (lane >= off) inc += t;
    }
    __shared__ int wsum[32];
    if (lane == 31) wsum[w] = inc;
    __syncthreads();
    if (w == 0) {
        int v = wsum[lane];
#pragma unroll
        for (int off = 1; off < 32; off <<= 1) {
            int t = __shfl_up_sync(0xFFFFFFFFu, v, off);
            if (lane >= off) v += t;
        }
        wsum[lane] = v;
    }
    __syncthreads();
    int base = (w > 0 ? wsum[w - 1] : 0) + inc - sum;
    if (beg < N_NODES) {
        int run = base;
        int4* rp = (int4*)(g_rowptr + beg);
#pragma unroll
        for (int i = 0; i < CH / 4; i++) {
            int4 o;
            o.x = run; run += vals[i * 4 + 0];
            o.y = run; run += vals[i * 4 + 1];
            o.z = run; run += vals[i * 4 + 2];
            o.w = run; run += vals[i * 4 + 3];
            rp[i] = o;
        }
    }
    if (tid == 0) g_rowptr[N_NODES] = wsum[31];
}

__global__ void scatter_kernel(const int* __restrict__ src, const int* __restrict__ dst) {
    int e = blockIdx.x * blockDim.x + threadIdx.x;
    if (e < N_EDGES) {
        int d = dst[e];
        int pos = g_rowptr[d] + atomicAdd(&g_cursor[d], 1);
        g_srcs[pos] = src[e];
    }
}

// ---------------- FP16 mma.sync GEMM (z-batched over 3 weight mats) ---------
#define BM 128
#define GBK 32
#define APH 40

__device__ __forceinline__ void cpasync16(void* smem, const void* g, int sz) {
    uint32_t sa = (uint32_t)__cvta_generic_to_shared(smem);
    asm volatile("cp.async.cg.shared.global [%0], [%1], 16, %2;\n"
                 :: "r"(sa), "l"(g), "r"(sz));
}

__device__ __forceinline__ void ldsm_x4(uint32_t& r0, uint32_t& r1,
                                        uint32_t& r2, uint32_t& r3, uint32_t addr) {
    asm volatile("ldmatrix.sync.aligned.m8n8.x4.shared.b16 {%0,%1,%2,%3}, [%4];"
                 : "=r"(r0), "=r"(r1), "=r"(r2), "=r"(r3) : "r"(addr));
}

template <int BNv, int JN>
__global__ __launch_bounds__(256, 2)
void gemm_f16_b3_kernel(const __half* __restrict__ A,
                        const __half* __restrict__ W0, const __half* __restrict__ W1,
                        const __half* __restrict__ W2,
                        __half* __restrict__ C0h, float* __restrict__ C1,
                        float* __restrict__ C2,
                        int M, int N, int K) {
    const __half* Wt = (blockIdx.z == 0) ? W0 : (blockIdx.z == 1) ? W1 : W2;

    extern __shared__ __half smemH[];
    __half (*As)[BM][APH]  = (__half (*)[BM][APH])smemH;
    __half (*Bs)[BNv][APH] = (__half (*)[BNv][APH])(smemH + 3 * BM * APH);

    int tid  = threadIdx.x;
    int warp = tid >> 5;
    int lane = tid & 31;
    int blockRow = blockIdx.y * BM;
    int blockCol = blockIdx.x * BNv;
    int wm = (warp >> 1) * 32;
    int wn = (warp & 1) * (JN * 8);

    float acc[2][JN][4];
#pragma unroll
    for (int i = 0; i < 2; i++)
#pragma unroll
        for (int j = 0; j < JN; j++)
#pragma unroll
            for (int t = 0; t < 4; t++) acc[i][j][t] = 0.f;

    auto loadStage = [&](int s, int k0) {
#pragma unroll
        for (int j = 0; j < 2; j++) {
            int c = tid + j * 256;
            int row = c >> 2, part = c & 3;
            int gRow = blockRow + row;
            int ok = (gRow < M);
            const __half* gp = A + (size_t)(ok ? gRow : 0) * K + k0 + part * 8;
            cpasync16(&As[s][row][part * 8], gp, ok ? 16 : 0);
        }
#pragma unroll
        for (int j = 0; j < BNv / 64; j++) {
            int c = tid + j * 256;
            int row = c >> 2, part = c & 3;
            const __half* gp = Wt + (size_t)(blockCol + row) * K + k0 + part * 8;
            cpasync16(&Bs[s][row][part * 8], gp, 16);
        }
        asm volatile("cp.async.commit_group;\n");
    };

    int aRow = wm + (lane & 15);
    int aCol = (lane >> 4) * 8;
    int bRow = wn + ((lane >> 4) << 3) + (lane & 7);
    int bCol = ((lane >> 3) & 1) * 8;

    int nK = K / GBK;
    loadStage(0, 0);
    loadStage(1, GBK);

    for (int kt = 0; kt < nK; kt++) {
        int s = kt % 3;
        if (kt + 2 < nK) {
            loadStage((kt + 2) % 3, (kt + 2) * GBK);
            asm volatile("cp.async.wait_group 2;\n");
        } else if (kt + 1 < nK) {
            asm volatile("cp.async.wait_group 1;\n");
        } else {
            asm volatile("cp.async.wait_group 0;\n");
        }
        __syncthreads();

#pragma unroll
        for (int ks = 0; ks < 2; ks++) {
            uint32_t aF[2][4];
#pragma unroll
            for (int i = 0; i < 2; i++) {
                uint32_t ad = smem_u32(&As[s][aRow + i * 16][aCol + ks * 16]);
                ldsm_x4(aF[i][0], aF[i][1], aF[i][2], aF[i][3], ad);
            }
            uint32_t bF[JN][2];
#pragma unroll
            for (int j = 0; j < JN; j += 2) {
                uint32_t bd = smem_u32(&Bs[s][bRow + j * 8][bCol + ks * 16]);
                ldsm_x4(bF[j][0], bF[j][1], bF[j + 1][0], bF[j + 1][1], bd);
            }
#pragma unroll
            for (int i = 0; i < 2; i++)
#pragma unroll
                for (int j = 0; j < JN; j++) {
                    asm volatile(
                        "mma.sync.aligned.m16n8k16.row.col.f32.f16.f16.f32 "
                        "{%0,%1,%2,%3}, {%4,%5,%6,%7}, {%8,%9}, {%0,%1,%2,%3};\n"
                        : "+f"(acc[i][j][0]), "+f"(acc[i][j][1]),
                          "+f"(acc[i][j][2]), "+f"(acc[i][j][3])
                        : "r"(aF[i][0]), "r"(aF[i][1]), "r"(aF[i][2]), "r"(aF[i][3]),
                          "r"(bF[j][0]), "r"(bF[j][1]));
                }
        }
        __syncthreads();
    }

    if (blockIdx.z == 0) {      // xl -> fp16
#pragma unroll
        for (int i = 0; i < 2; i++) {
#pragma unroll
            for (int j = 0; j < JN; j++) {
                int r0 = blockRow + wm + i * 16 + (lane >> 2);
                int c0 = blockCol + wn + j * 8 + (lane & 3) * 2;
                if (r0 < M)
                    *(__half2*)(C0h + (size_t)r0 * N + c0) =
                        __floats2half2_rn(acc[i][j][0], acc[i][j][1]);
                if (r0 + 8 < M)
                    *(__half2*)(C0h + (size_t)(r0 + 8) * N + c0) =
                        __floats2half2_rn(acc[i][j][2], acc[i][j][3]);
            }
        }
    } else {                    // xr / sk -> fp32
        float* C = (blockIdx.z == 1) ? C1 : C2;
#pragma unroll
        for (int i = 0; i < 2; i++) {
#pragma unroll
            for (int j = 0; j < JN; j++) {
                int r0 = blockRow + wm + i * 16 + (lane >> 2);
                int c0 = blockCol + wn + j * 8 + (lane & 3) * 2;
                if (r0 < M) {
                    float2 v = make_float2(acc[i][j][0], acc[i][j][1]);
                    *(float2*)(C + (size_t)r0 * N + c0) = v;
                }
                if (r0 + 8 < M) {
                    float2 v = make_float2(acc[i][j][2], acc[i][j][3]);
                    *(float2*)(C + (size_t)(r0 + 8) * N + c0) = v;
                }
            }
        }
    }
}

#define GEMM_SMEM(BNv) (3 * (BM * APH + (BNv) * APH) * 2)

// ---------------- fused edge phase: score + online softmax + aggregate ------
// 2-way edge pipelining: two gathers + two independent score reductions in
// flight; combined online-softmax update (algebraically identical to two
// sequential updates).
template <int NK4>   // 4-elem chunks per lane; D = NK4*128
__global__ void gat_edge_fused_kernel(const __half* __restrict__ xl,
                                      const float* __restrict__ xr,
                                      const float* __restrict__ att,
                                      const float* __restrict__ sk,
                                      const float* __restrict__ bc,
                                      const float* __restrict__ bs,
                                      float* __restrict__ out,
                                      __half* __restrict__ outh,
                                      int doRelu) {
    const int D = NK4 * 128;
    int v = (blockIdx.x * blockDim.x + threadIdx.x) >> 5;
    if (v >= N_NODES) return;
    int lane = threadIdx.x & 31;
    int beg = g_rowptr[v], end = g_rowptr[v + 1];

    const float4* xr4  = (const float4*)(xr + (size_t)v * D);
    const float4* att4 = (const float4*)att;
    float4 xrv[NK4], atv[NK4], acc[NK4];
#pragma unroll
    for (int k = 0; k < NK4; k++) {
        xrv[k] = xr4[lane + 32 * k];
        atv[k] = att4[lane + 32 * k];
        acc[k] = make_float4(0.f, 0.f, 0.f, 0.f);
    }

    float m = -INFINITY, ssum = 0.f;
    int i = beg;
    for (; i + 1 < end; i += 2) {
        int s0 = g_srcs[i], s1 = g_srcs[i + 1];
        const uint2* xs0 = (const uint2*)(xl + (size_t)s0 * D);
        const uint2* xs1 = (const uint2*)(xl + (size_t)s1 * D);
        uint2 raw0[NK4], raw1[NK4];
#pragma unroll
        for (int k = 0; k < NK4; k++) { raw0[k] = xs0[lane + 32 * k]; raw1[k] = xs1[lane + 32 * k]; }

        float4 vx0[NK4], vx1[NK4];
        float sc0 = 0.f, sc1 = 0.f;
#pragma unroll
        for (int k = 0; k < NK4; k++) {
            float2 a01 = __half22float2(*(__half2*)&raw0[k].x);
            float2 a23 = __half22float2(*(__half2*)&raw0[k].y);
            vx0[k] = make_float4(a01.x, a01.y, a23.x, a23.y);
            float2 b01 = __half22float2(*(__half2*)&raw1[k].x);
            float2 b23 = __half22float2(*(__half2*)&raw1[k].y);
            vx1[k] = make_float4(b01.x, b01.y, b23.x, b23.y);
            float t;
            t = vx0[k].x + xrv[k].x; sc0 = fmaf((t > 0.f ? t : 0.2f * t), atv[k].x, sc0);
            t = vx1[k].x + xrv[k].x; sc1 = fmaf((t > 0.f ? t : 0.2f * t), atv[k].x, sc1);
            t = vx0[k].y + xrv[k].y; sc0 = fmaf((t > 0.f ? t : 0.2f * t), atv[k].y, sc0);
            t = vx1[k].y + xrv[k].y; sc1 = fmaf((t > 0.f ? t : 0.2f * t), atv[k].y, sc1);
            t = vx0[k].z + xrv[k].z; sc0 = fmaf((t > 0.f ? t : 0.2f * t), atv[k].z, sc0);
            t = vx1[k].z + xrv[k].z; sc1 = fmaf((t > 0.f ? t : 0.2f * t), atv[k].z, sc1);
            t = vx0[k].w + xrv[k].w; sc0 = fmaf((t > 0.f ? t : 0.2f * t), atv[k].w, sc0);
            t = vx1[k].w + xrv[k].w; sc1 = fmaf((t > 0.f ? t : 0.2f * t), atv[k].w, sc1);
        }
#pragma unroll
        for (int off = 16; off > 0; off >>= 1) {
            sc0 += __shfl_xor_sync(0xFFFFFFFFu, sc0, off);
            sc1 += __shfl_xor_sync(0xFFFFFFFFu, sc1, off);
        }

        float mn = fmaxf(m, fmaxf(sc0, sc1));
        float scale = __expf(m - mn);
        float w0 = __expf(sc0 - mn);
        float w1 = __expf(sc1 - mn);
        ssum = ssum * scale + w0 + w1;
#pragma unroll
        for (int k = 0; k < NK4; k++) {
            acc[k].x = fmaf(acc[k].x, scale, fmaf(w0, vx0[k].x, w1 * vx1[k].x));
            acc[k].y = fmaf(acc[k].y, scale, fmaf(w0, vx0[k].y, w1 * vx1[k].y));
            acc[k].z = fmaf(acc[k].z, scale, fmaf(w0, vx0[k].z, w1 * vx1[k].z));
            acc[k].w = fmaf(acc[k].w, scale, fmaf(w0, vx0[k].w, w1 * vx1[k].w));
        }
        m = mn;
    }
    for (; i < end; i++) {      // remainder (0 or 1 edge)
        int s = g_srcs[i];
        const uint2* xs = (const uint2*)(xl + (size_t)s * D);
        float4 vx[NK4];
        float sc = 0.f;
#pragma unroll
        for (int k = 0; k < NK4; k++) {
            uint2 raw = xs[lane + 32 * k];
            float2 f01 = __half22float2(*(__half2*)&raw.x);
            float2 f23 = __half22float2(*(__half2*)&raw.y);
            vx[k] = make_float4(f01.x, f01.y, f23.x, f23.y);
            float t;
            t = vx[k].x + xrv[k].x; sc = fmaf((t > 0.f ? t : 0.2f * t), atv[k].x, sc);
            t = vx[k].y + xrv[k].y; sc = fmaf((t > 0.f ? t : 0.2f * t), atv[k].y, sc);
            t = vx[k].z + xrv[k].z; sc = fmaf((t > 0.f ? t : 0.2f * t), atv[k].z, sc);
            t = vx[k].w + xrv[k].w; sc = fmaf((t > 0.f ? t : 0.2f * t), atv[k].w, sc);
        }
#pragma unroll
        for (int off = 16; off > 0; off >>= 1)
            sc += __shfl_xor_sync(0xFFFFFFFFu, sc, off);
        float mn = fmaxf(m, sc);
        float scale = __expf(m - mn);
        float w = __expf(sc - mn);
        ssum = ssum * scale + w;
#pragma unroll
        for (int k = 0; k < NK4; k++) {
            acc[k].x = fmaf(acc[k].x, scale, w * vx[k].x);
            acc[k].y = fmaf(acc[k].y, scale, w * vx[k].y);
            acc[k].z = fmaf(acc[k].z, scale, w * vx[k].z);
            acc[k].w = fmaf(acc[k].w, scale, w * vx[k].w);
        }
        m = mn;
    }

    float inv = 1.f / (ssum + 1e-16f);
    const float4* bc4 = (const float4*)bc;
    const float4* bs4 = (const float4*)bs;
    const float4* sk4 = (const float4*)(sk + (size_t)v * D);
#pragma unroll
    for (int k = 0; k < NK4; k++) {
        int idx = lane + 32 * k;
        float4 vbc = bc4[idx], vbs = bs4[idx], vsk = sk4[idx];
        float4 o;
        o.x = fmaf(acc[k].x, inv, vbc.x + vbs.x + vsk.x);
        o.y = fmaf(acc[k].y, inv, vbc.y + vbs.y + vsk.y);
        o.z = fmaf(acc[k].z, inv, vbc.z + vbs.z + vsk.z);
        o.w = fmaf(acc[k].w, inv, vbc.w + vbs.w + vsk.w);
        if (doRelu) {
            o.x = fmaxf(o.x, 0.f); o.y = fmaxf(o.y, 0.f);
            o.z = fmaxf(o.z, 0.f); o.w = fmaxf(o.w, 0.f);
        }
        if (outh) {
            __half2* oh = (__half2*)(outh + (size_t)v * D) + idx * 2;
            oh[0] = __floats2half2_rn(o.x, o.y);
            oh[1] = __floats2half2_rn(o.z, o.w);
        } else {
            ((float4*)(out + (size_t)v * D))[idx] = o;
        }
    }
}

// ---------------- host-side orchestration -----------------------------------
static void run_layer(const __half* A, int K, int D,
                      const __half* Wt_l, const __half* Wt_r, const __half* Wt_s,
                      const float* att, const float* bc, const float* bs,
                      float* out, __half* outh, int doRelu,
                      __half* xlh, float* xr, float* sk) {
    if (D >= 256) {
        dim3 gg(D / 128, (N_NODES + BM - 1) / BM, 3);
        gemm_f16_b3_kernel<128, 8><<<gg, 256, GEMM_SMEM(128)>>>(
            A, Wt_l, Wt_r, Wt_s, xlh, xr, sk, N_NODES, D, K);
    } else {
        dim3 gg(D / 64, (N_NODES + BM - 1) / BM, 3);
        gemm_f16_b3_kernel<64, 4><<<gg, 256, GEMM_SMEM(64)>>>(
            A, Wt_l, Wt_r, Wt_s, xlh, xr, sk, N_NODES, D, K);
    }

    int warpsPerBlock = 8;
    int nbv = (N_NODES + warpsPerBlock - 1) / warpsPerBlock;
    if (D == 512)
        gat_edge_fused_kernel<4><<<nbv, warpsPerBlock * 32>>>(xlh, xr, att, sk, bc, bs, out, outh, doRelu);
    else if (D == 256)
        gat_edge_fused_kernel<2><<<nbv, warpsPerBlock * 32>>>(xlh, xr, att, sk, bc, bs, out, outh, doRelu);
    else
        gat_edge_fused_kernel<1><<<nbv, warpsPerBlock * 32>>>(xlh, xr, att, sk, bc, bs, out, outh, doRelu);
}

extern "C" void kernel_launch(void* const* d_in, const int* in_sizes, int n_in,
                              void* d_out, int out_size) {
    const float* x  = (const float*)d_in[0];
    const int*   ei = (const int*)d_in[1];
    const int* src = ei;
    const int* dst = ei + N_EDGES;

    const float* Wl[3]  = {(const float*)d_in[2],  (const float*)d_in[8],  (const float*)d_in[14]};
    const float* Wr[3]  = {(const float*)d_in[3],  (const float*)d_in[9],  (const float*)d_in[15]};
    const float* att[3] = {(const float*)d_in[4],  (const float*)d_in[10], (const float*)d_in[16]};
    const float* bc[3]  = {(const float*)d_in[5],  (const float*)d_in[11], (const float*)d_in[17]};
    const float* Ws[3]  = {(const float*)d_in[6],  (const float*)d_in[12], (const float*)d_in[18]};
    const float* bs[3]  = {(const float*)d_in[7],  (const float*)d_in[13], (const float*)d_in[19]};

    float *xr, *sk;
    __half *xlh, *h1h, *h2h, *xah, *wth;
    cudaGetSymbolAddress((void**)&xlh, g_xlh);
    cudaGetSymbolAddress((void**)&xr,  g_xr);
    cudaGetSymbolAddress((void**)&sk,  g_sk);
    cudaGetSymbolAddress((void**)&h1h, g_h1h);
    cudaGetSymbolAddress((void**)&h2h, g_h2h);
    cudaGetSymbolAddress((void**)&xah, g_xah);
    cudaGetSymbolAddress((void**)&wth, g_wth);

    (void)cudaFuncSetAttribute(gemm_f16_b3_kernel<128, 8>,
                               cudaFuncAttributeMaxDynamicSharedMemorySize, GEMM_SMEM(128));
    (void)cudaFuncSetAttribute(gemm_f16_b3_kernel<64, 4>,
                               cudaFuncAttributeMaxDynamicSharedMemorySize, GEMM_SMEM(64));

    // merged prepass (one launch): transpose+fp16 weights, fp16 x, zero counts
    int wK[9] = {256, 256, 256, 512, 512, 512, 256, 256, 256};
    int wN[9] = {512, 512, 512, 256, 256, 256, 128, 128, 128};
    const float* wsrc[9] = {Wl[0], Wr[0], Ws[0], Wl[1], Wr[1], Ws[1], Wl[2], Wr[2], Ws[2]};
    __half* wdst[9];
    {
        int off = 0;
        for (int i = 0; i < 9; i++) { wdst[i] = wth + off; off += wK[i] * wN[i]; }
    }
    PrepArgs pa;
    for (int i = 0; i < 9; i++) {
        pa.wsrc[i] = wsrc[i]; pa.wdst[i] = wdst[i];
        pa.K[i] = wK[i]; pa.N[i] = wN[i];
    }
    pa.xsrc = x; pa.xdst = xah; pa.xn4 = N_NODES * 256 / 4;
    prep_kernel<<<dim3(160, 11), 256>>>(pa);

    // CSR build (counting sort of edges by dst)
    hist_kernel<<<(N_EDGES + 255) / 256, 256>>>(dst);
    scan_kernel<<<1, 1024>>>();
    scatter_kernel<<<(N_EDGES + 255) / 256, 256>>>(src, dst);

    // Layer 1: 256 -> 512, relu, fp16 out for next GEMM
    run_layer(xah, 256, 512, wdst[0], wdst[1], wdst[2], att[0], bc[0], bs[0],
              nullptr, h1h, 1, xlh, xr, sk);
    // Layer 2: 512 -> 256, relu, fp16 out
    run_layer(h1h, 512, 256, wdst[3], wdst[4], wdst[5], att[1], bc[1], bs[1],
              nullptr, h2h, 1, xlh, xr, sk);
    // Layer 3: 256 -> 128, no relu, fp32 output
    run_layer(h2h, 256, 128, wdst[6], wdst[7], wdst[8], att[2], bc[2], bs[2],
              (float*)d_out, nullptr, 0, xlh, xr, sk);
}

// round 17
// speedup vs baseline: 1.5738x; 1.0122x over previous
#include <cuda_runtime.h>
#include <cuda_fp16.h>
#include <cstdint>
#include <stdint.h>
#include <math.h>

#define N_NODES 20000
#define N_EDGES 320000
#define DMAX    512

// ---------------- scratch (static device globals; no allocation allowed) ----
__device__ __align__(16) __half g_xlh[N_NODES * DMAX];  // fp16 xl (edge-gather operand)
__device__ __align__(16) float  g_xr[N_NODES * DMAX];
__device__ __align__(16) float  g_sk[N_NODES * DMAX];
__device__ __align__(16) __half g_h1h[N_NODES * 512];   // fp16 activations (GEMM A input)
__device__ __align__(16) __half g_h2h[N_NODES * 256];
__device__ __align__(16) __half g_xah[N_NODES * 256];   // fp16 copy of x
__device__ __align__(16) __half g_wth[900000];          // fp16 transposed weights [N][K]
__device__ __align__(16) int    g_srcs [N_EDGES];
__device__ __align__(16) int    g_count [N_NODES];
__device__ __align__(16) int    g_cursor[N_NODES];
__device__ __align__(16) int    g_rowptr[N_NODES + 4];

__device__ __forceinline__ uint32_t smem_u32(const void* p) {
    return (uint32_t)__cvta_generic_to_shared(p);
}

// ------- merged prepass: transpose+fp16 9 weights, fp16 x, zero counts ------
struct PrepArgs {
    const float* wsrc[9];
    __half*      wdst[9];
    int          K[9], N[9];
    const float* xsrc;
    __half*      xdst;
    int          xn4;
};

__global__ void prep_kernel(PrepArgs pa) {
    int s = blockIdx.y;
    if (s == 9) {   // x -> fp16
        const float4* in = (const float4*)pa.xsrc;
        for (int i = blockIdx.x * blockDim.x + threadIdx.x; i < pa.xn4;
             i += gridDim.x * blockDim.x) {
            float4 v = in[i];
            __half2* o = (__half2*)(pa.xdst + (size_t)i * 4);
            o[0] = __floats2half2_rn(v.x, v.y);
            o[1] = __floats2half2_rn(v.z, v.w);
        }
        return;
    }
    if (s == 10) {  // zero count/cursor
        int4 z = make_int4(0, 0, 0, 0);
        for (int i = blockIdx.x * blockDim.x + threadIdx.x; i < N_NODES / 4;
             i += gridDim.x * blockDim.x) {
            ((int4*)g_count)[i]  = z;
            ((int4*)g_cursor)[i] = z;
        }
        return;
    }
    // transpose + convert: Wt[n][k] = fp16(W[k][n])
    int K = pa.K[s], N = pa.N[s];
    const float* src = pa.wsrc[s];
    __half*      dst = pa.wdst[s];
    int tpn = N / 32, tpk = K / 32, nt = tpn * tpk;
    __shared__ float tile[32][33];
    int tx = threadIdx.x & 31, ty = threadIdx.x >> 5;   // 32x8
    for (int t = blockIdx.x; t < nt; t += gridDim.x) {
        int n0 = (t % tpn) * 32, k0 = (t / tpn) * 32;
#pragma unroll
        for (int i = 0; i < 4; i++)
            tile[ty + 8 * i][tx] = src[(size_t)(k0 + ty + 8 * i) * N + n0 + tx];
        __syncthreads();
#pragma unroll
        for (int i = 0; i < 4; i++)
            dst[(size_t)(n0 + ty + 8 * i) * K + k0 + tx] = __float2half(tile[tx][ty + 8 * i]);
        __syncthreads();
    }
}

// ---------------- CSR build (counting sort by dst) --------------------------
__global__ void hist_kernel(const int* __restrict__ dst) {
    int e = blockIdx.x * blockDim.x + threadIdx.x;
    if (e < N_EDGES) atomicAdd(&g_count[dst[e]], 1);
}

__global__ void scan_kernel() {
    const int CH = 20;
    int tid = threadIdx.x;
    int lane = tid & 31, w = tid >> 5;
    int beg = tid * CH;
    int vals[CH];
    int sum = 0;
    if (beg < N_NODES) {
        const int4* p = (const int4*)(g_count + beg);
#pragma unroll
        for (int i = 0; i < CH / 4; i++) {
            int4 v = p[i];
            vals[i * 4 + 0] = v.x; vals[i * 4 + 1] = v.y;
            vals[i * 4 + 2] = v.z; vals[i * 4 + 3] = v.w;
            sum += v.x + v.y + v.z + v.w;
        }
    }
    int inc = sum;
#pragma unroll
    for (int off = 1; off < 32; off <<= 1) {
        int t = __shfl_up_sync(0xFFFFFFFFu, inc, off);
        if (lane >= off) inc += t;
    }
    __shared__ int wsum[32];
    if (lane == 31) wsum[w] = inc;
    __syncthreads();
    if (w == 0) {
        int v = wsum[lane];
#pragma unroll
        for (int off = 1; off < 32; off <<= 1) {
            int t = __shfl_up_sync(0xFFFFFFFFu, v, off);
            if (lane >= off) v += t;
        }
        wsum[lane] = v;
    }
    __syncthreads();
    int base = (w > 0 ? wsum[w - 1] : 0) + inc - sum;
    if (beg < N_NODES) {
        int run = base;
        int4* rp = (int4*)(g_rowptr + beg);
#pragma unroll
        for (int i = 0; i < CH / 4; i++) {
            int4 o;
            o.x = run; run += vals[i * 4 + 0];
            o.y = run; run += vals[i * 4 + 1];
            o.z = run; run += vals[i * 4 + 2];
            o.w = run; run += vals[i * 4 + 3];
            rp[i] = o;
        }
    }
    if (tid == 0) g_rowptr[N_NODES] = wsum[31];
}

__global__ void scatter_kernel(const int* __restrict__ src, const int* __restrict__ dst) {
    int e = blockIdx.x * blockDim.x + threadIdx.x;
    if (e < N_EDGES) {
        int d = dst[e];
        int pos = g_rowptr[d] + atomicAdd(&g_cursor[d], 1);
        g_srcs[pos] = src[e];
    }
}

// ---------------- FP16 mma.sync GEMM (z-batched over 3 weight mats) ---------
// 4-stage cp.async pipeline, ONE __syncthreads per k-tile:
//   iter kt: wait(stage kt ready) -> sync -> load stage kt+3 -> mma(stage kt)
// Stage (kt+3)%4 was last consumed at kt-1; sync(kt) orders all warps past
// mma(kt-1), so the overwrite is safe with a single barrier.
#define BM 128
#define GBK 32
#define APH 40

__device__ __forceinline__ void cpasync16(void* smem, const void* g, int sz) {
    uint32_t sa = (uint32_t)__cvta_generic_to_shared(smem);
    asm volatile("cp.async.cg.shared.global [%0], [%1], 16, %2;\n"
                 :: "r"(sa), "l"(g), "r"(sz));
}

__device__ __forceinline__ void ldsm_x4(uint32_t& r0, uint32_t& r1,
                                        uint32_t& r2, uint32_t& r3, uint32_t addr) {
    asm volatile("ldmatrix.sync.aligned.m8n8.x4.shared.b16 {%0,%1,%2,%3}, [%4];"
                 : "=r"(r0), "=r"(r1), "=r"(r2), "=r"(r3) : "r"(addr));
}

template <int BNv, int JN>
__global__ __launch_bounds__(256, 2)
void gemm_f16_b3_kernel(const __half* __restrict__ A,
                        const __half* __restrict__ W0, const __half* __restrict__ W1,
                        const __half* __restrict__ W2,
                        __half* __restrict__ C0h, float* __restrict__ C1,
                        float* __restrict__ C2,
                        int M, int N, int K) {
    const __half* Wt = (blockIdx.z == 0) ? W0 : (blockIdx.z == 1) ? W1 : W2;

    extern __shared__ __half smemH[];
    __half (*As)[BM][APH]  = (__half (*)[BM][APH])smemH;
    __half (*Bs)[BNv][APH] = (__half (*)[BNv][APH])(smemH + 4 * BM * APH);

    int tid  = threadIdx.x;
    int warp = tid >> 5;
    int lane = tid & 31;
    int blockRow = blockIdx.y * BM;
    int blockCol = blockIdx.x * BNv;
    int wm = (warp >> 1) * 32;
    int wn = (warp & 1) * (JN * 8);

    float acc[2][JN][4];
#pragma unroll
    for (int i = 0; i < 2; i++)
#pragma unroll
        for (int j = 0; j < JN; j++)
#pragma unroll
            for (int t = 0; t < 4; t++) acc[i][j][t] = 0.f;

    auto loadStage = [&](int s, int k0) {
#pragma unroll
        for (int j = 0; j < 2; j++) {
            int c = tid + j * 256;
            int row = c >> 2, part = c & 3;
            int gRow = blockRow + row;
            int ok = (gRow < M);
            const __half* gp = A + (size_t)(ok ? gRow : 0) * K + k0 + part * 8;
            cpasync16(&As[s][row][part * 8], gp, ok ? 16 : 0);
        }
#pragma unroll
        for (int j = 0; j < BNv / 64; j++) {
            int c = tid + j * 256;
            int row = c >> 2, part = c & 3;
            const __half* gp = Wt + (size_t)(blockCol + row) * K + k0 + part * 8;
            cpasync16(&Bs[s][row][part * 8], gp, 16);
        }
        asm volatile("cp.async.commit_group;\n");
    };

    int aRow = wm + (lane & 15);
    int aCol = (lane >> 4) * 8;
    int bRow = wn + ((lane >> 4) << 3) + (lane & 7);
    int bCol = ((lane >> 3) & 1) * 8;

    int nK = K / GBK;   // >= 8 here
    loadStage(0, 0);
    loadStage(1, GBK);
    loadStage(2, 2 * GBK);

    for (int kt = 0; kt < nK; kt++) {
        int s = kt & 3;
        // make stage kt ready: outstanding groups are kt, kt+1, kt+2 (and none older)
        if (kt + 2 < nK) {
            asm volatile("cp.async.wait_group 2;\n");
        } else if (kt + 1 < nK) {
            asm volatile("cp.async.wait_group 1;\n");
        } else {
            asm volatile("cp.async.wait_group 0;\n");
        }
        __syncthreads();
        if (kt + 3 < nK)
            loadStage((kt + 3) & 3, (kt + 3) * GBK);

#pragma unroll
        for (int ks = 0; ks < 2; ks++) {
            uint32_t aF[2][4];
#pragma unroll
            for (int i = 0; i < 2; i++) {
                uint32_t ad = smem_u32(&As[s][aRow + i * 16][aCol + ks * 16]);
                ldsm_x4(aF[i][0], aF[i][1], aF[i][2], aF[i][3], ad);
            }
            uint32_t bF[JN][2];
#pragma unroll
            for (int j = 0; j < JN; j += 2) {
                uint32_t bd = smem_u32(&Bs[s][bRow + j * 8][bCol + ks * 16]);
                ldsm_x4(bF[j][0], bF[j][1], bF[j + 1][0], bF[j + 1][1], bd);
            }
#pragma unroll
            for (int i = 0; i < 2; i++)
#pragma unroll
                for (int j = 0; j < JN; j++) {
                    asm volatile(
                        "mma.sync.aligned.m16n8k16.row.col.f32.f16.f16.f32 "
                        "{%0,%1,%2,%3}, {%4,%5,%6,%7}, {%8,%9}, {%0,%1,%2,%3};\n"
                        : "+f"(acc[i][j][0]), "+f"(acc[i][j][1]),
                          "+f"(acc[i][j][2]), "+f"(acc[i][j][3])
                        : "r"(aF[i][0]), "r"(aF[i][1]), "r"(aF[i][2]), "r"(aF[i][3]),
                          "r"(bF[j][0]), "r"(bF[j][1]));
                }
        }
    }

    if (blockIdx.z == 0) {      // xl -> fp16
#pragma unroll
        for (int i = 0; i < 2; i++) {
#pragma unroll
            for (int j = 0; j < JN; j++) {
                int r0 = blockRow + wm + i * 16 + (lane >> 2);
                int c0 = blockCol + wn + j * 8 + (lane & 3) * 2;
                if (r0 < M)
                    *(__half2*)(C0h + (size_t)r0 * N + c0) =
                        __floats2half2_rn(acc[i][j][0], acc[i][j][1]);
                if (r0 + 8 < M)
                    *(__half2*)(C0h + (size_t)(r0 + 8) * N + c0) =
                        __floats2half2_rn(acc[i][j][2], acc[i][j][3]);
            }
        }
    } else {                    // xr / sk -> fp32
        float* C = (blockIdx.z == 1) ? C1 : C2;
#pragma unroll
        for (int i = 0; i < 2; i++) {
#pragma unroll
            for (int j = 0; j < JN; j++) {
                int r0 = blockRow + wm + i * 16 + (lane >> 2);
                int c0 = blockCol + wn + j * 8 + (lane & 3) * 2;
                if (r0 < M) {
                    float2 v = make_float2(acc[i][j][0], acc[i][j][1]);
                    *(float2*)(C + (size_t)r0 * N + c0) = v;
                }
                if (r0 + 8 < M) {
                    float2 v = make_float2(acc[i][j][2], acc[i][j][3]);
                    *(float2*)(C + (size_t)(r0 + 8) * N + c0) = v;
                }
            }
        }
    }
}

#define GEMM_SMEM(BNv) (4 * (BM * APH + (BNv) * APH) * 2)

// ---------------- fused edge phase: score + online softmax + aggregate ------
// 2-way edge pipelining; combined online-softmax update.
template <int NK4>   // 4-elem chunks per lane; D = NK4*128
__global__ void gat_edge_fused_kernel(const __half* __restrict__ xl,
                                      const float* __restrict__ xr,
                                      const float* __restrict__ att,
                                      const float* __restrict__ sk,
                                      const float* __restrict__ bc,
                                      const float* __restrict__ bs,
                                      float* __restrict__ out,
                                      __half* __restrict__ outh,
                                      int doRelu) {
    const int D = NK4 * 128;
    int v = (blockIdx.x * blockDim.x + threadIdx.x) >> 5;
    if (v >= N_NODES) return;
    int lane = threadIdx.x & 31;
    int beg = g_rowptr[v], end = g_rowptr[v + 1];

    const float4* xr4  = (const float4*)(xr + (size_t)v * D);
    const float4* att4 = (const float4*)att;
    float4 xrv[NK4], atv[NK4], acc[NK4];
#pragma unroll
    for (int k = 0; k < NK4; k++) {
        xrv[k] = xr4[lane + 32 * k];
        atv[k] = att4[lane + 32 * k];
        acc[k] = make_float4(0.f, 0.f, 0.f, 0.f);
    }

    float m = -INFINITY, ssum = 0.f;
    int i = beg;
    for (; i + 1 < end; i += 2) {
        int s0 = g_srcs[i], s1 = g_srcs[i + 1];
        const uint2* xs0 = (const uint2*)(xl + (size_t)s0 * D);
        const uint2* xs1 = (const uint2*)(xl + (size_t)s1 * D);
        uint2 raw0[NK4], raw1[NK4];
#pragma unroll
        for (int k = 0; k < NK4; k++) { raw0[k] = xs0[lane + 32 * k]; raw1[k] = xs1[lane + 32 * k]; }

        float4 vx0[NK4], vx1[NK4];
        float sc0 = 0.f, sc1 = 0.f;
#pragma unroll
        for (int k = 0; k < NK4; k++) {
            float2 a01 = __half22float2(*(__half2*)&raw0[k].x);
            float2 a23 = __half22float2(*(__half2*)&raw0[k].y);
            vx0[k] = make_float4(a01.x, a01.y, a23.x, a23.y);
            float2 b01 = __half22float2(*(__half2*)&raw1[k].x);
            float2 b23 = __half22float2(*(__half2*)&raw1[k].y);
            vx1[k] = make_float4(b01.x, b01.y, b23.x, b23.y);
            float t;
            t = vx0[k].x + xrv[k].x; sc0 = fmaf((t > 0.f ? t : 0.2f * t), atv[k].x, sc0);
            t = vx1[k].x + xrv[k].x; sc1 = fmaf((t > 0.f ? t : 0.2f * t), atv[k].x, sc1);
            t = vx0[k].y + xrv[k].y; sc0 = fmaf((t > 0.f ? t : 0.2f * t), atv[k].y, sc0);
            t = vx1[k].y + xrv[k].y; sc1 = fmaf((t > 0.f ? t : 0.2f * t), atv[k].y, sc1);
            t = vx0[k].z + xrv[k].z; sc0 = fmaf((t > 0.f ? t : 0.2f * t), atv[k].z, sc0);
            t = vx1[k].z + xrv[k].z; sc1 = fmaf((t > 0.f ? t : 0.2f * t), atv[k].z, sc1);
            t = vx0[k].w + xrv[k].w; sc0 = fmaf((t > 0.f ? t : 0.2f * t), atv[k].w, sc0);
            t = vx1[k].w + xrv[k].w; sc1 = fmaf((t > 0.f ? t : 0.2f * t), atv[k].w, sc1);
        }
#pragma unroll
        for (int off = 16; off > 0; off >>= 1) {
            sc0 += __shfl_xor_sync(0xFFFFFFFFu, sc0, off);
            sc1 += __shfl_xor_sync(0xFFFFFFFFu, sc1, off);
        }

        float mn = fmaxf(m, fmaxf(sc0, sc1));
        float scale = __expf(m - mn);
        float w0 = __expf(sc0 - mn);
        float w1 = __expf(sc1 - mn);
        ssum = ssum * scale + w0 + w1;
#pragma unroll
        for (int k = 0; k < NK4; k++) {
            acc[k].x = fmaf(acc[k].x, scale, fmaf(w0, vx0[k].x, w1 * vx1[k].x));
            acc[k].y = fmaf(acc[k].y, scale, fmaf(w0, vx0[k].y, w1 * vx1[k].y));
            acc[k].z = fmaf(acc[k].z, scale, fmaf(w0, vx0[k].z, w1 * vx1[k].z));
            acc[k].w = fmaf(acc[k].w, scale, fmaf(w0, vx0[k].w, w1 * vx1[k].w));
        }
        m = mn;
    }
    for (; i < end; i++) {      // remainder (0 or 1 edge)
        int s = g_srcs[i];
        const uint2* xs = (const uint2*)(xl + (size_t)s * D);
        float4 vx[NK4];
        float sc = 0.f;
#pragma unroll
        for (int k = 0; k < NK4; k++) {
            uint2 raw = xs[lane + 32 * k];
            float2 f01 = __half22float2(*(__half2*)&raw.x);
            float2 f23 = __half22float2(*(__half2*)&raw.y);
            vx[k] = make_float4(f01.x, f01.y, f23.x, f23.y);
            float t;
            t = vx[k].x + xrv[k].x; sc = fmaf((t > 0.f ? t : 0.2f * t), atv[k].x, sc);
            t = vx[k].y + xrv[k].y; sc = fmaf((t > 0.f ? t : 0.2f * t), atv[k].y, sc);
            t = vx[k].z + xrv[k].z; sc = fmaf((t > 0.f ? t : 0.2f * t), atv[k].z, sc);
            t = vx[k].w + xrv[k].w; sc = fmaf((t > 0.f ? t : 0.2f * t), atv[k].w, sc);
        }
#pragma unroll
        for (int off = 16; off > 0; off >>= 1)
            sc += __shfl_xor_sync(0xFFFFFFFFu, sc, off);
        float mn = fmaxf(m, sc);
        float scale = __expf(m - mn);
        float w = __expf(sc - mn);
        ssum = ssum * scale + w;
#pragma unroll
        for (int k = 0; k < NK4; k++) {
            acc[k].x = fmaf(acc[k].x, scale, w * vx[k].x);
            acc[k].y = fmaf(acc[k].y, scale, w * vx[k].y);
            acc[k].z = fmaf(acc[k].z, scale, w * vx[k].z);
            acc[k].w = fmaf(acc[k].w, scale, w * vx[k].w);
        }
        m = mn;
    }

    float inv = 1.f / (ssum + 1e-16f);
    const float4* bc4 = (const float4*)bc;
    const float4* bs4 = (const float4*)bs;
    const float4* sk4 = (const float4*)(sk + (size_t)v * D);
#pragma unroll
    for (int k = 0; k < NK4; k++) {
        int idx = lane + 32 * k;
        float4 vbc = bc4[idx], vbs = bs4[idx], vsk = sk4[idx];
        float4 o;
        o.x = fmaf(acc[k].x, inv, vbc.x + vbs.x + vsk.x);
        o.y = fmaf(acc[k].y, inv, vbc.y + vbs.y + vsk.y);
        o.z = fmaf(acc[k].z, inv, vbc.z + vbs.z + vsk.z);
        o.w = fmaf(acc[k].w, inv, vbc.w + vbs.w + vsk.w);
        if (doRelu) {
            o.x = fmaxf(o.x, 0.f); o.y = fmaxf(o.y, 0.f);
            o.z = fmaxf(o.z, 0.f); o.w = fmaxf(o.w, 0.f);
        }
        if (outh) {
            __half2* oh = (__half2*)(outh + (size_t)v * D) + idx * 2;
            oh[0] = __floats2half2_rn(o.x, o.y);
            oh[1] = __floats2half2_rn(o.z, o.w);
        } else {
            ((float4*)(out + (size_t)v * D))[idx] = o;
        }
    }
}

// ---------------- host-side orchestration -----------------------------------
static void run_layer(const __half* A, int K, int D,
                      const __half* Wt_l, const __half* Wt_r, const __half* Wt_s,
                      const float* att, const float* bc, const float* bs,
                      float* out, __half* outh, int doRelu,
                      __half* xlh, float* xr, float* sk) {
    if (D >= 256) {
        dim3 gg(D / 128, (N_NODES + BM - 1) / BM, 3);
        gemm_f16_b3_kernel<128, 8><<<gg, 256, GEMM_SMEM(128)>>>(
            A, Wt_l, Wt_r, Wt_s, xlh, xr, sk, N_NODES, D, K);
    } else {
        dim3 gg(D / 64, (N_NODES + BM - 1) / BM, 3);
        gemm_f16_b3_kernel<64, 4><<<gg, 256, GEMM_SMEM(64)>>>(
            A, Wt_l, Wt_r, Wt_s, xlh, xr, sk, N_NODES, D, K);
    }

    int warpsPerBlock = 8;
    int nbv = (N_NODES + warpsPerBlock - 1) / warpsPerBlock;
    if (D == 512)
        gat_edge_fused_kernel<4><<<nbv, warpsPerBlock * 32>>>(xlh, xr, att, sk, bc, bs, out, outh, doRelu);
    else if (D == 256)
        gat_edge_fused_kernel<2><<<nbv, warpsPerBlock * 32>>>(xlh, xr, att, sk, bc, bs, out, outh, doRelu);
    else
        gat_edge_fused_kernel<1><<<nbv, warpsPerBlock * 32>>>(xlh, xr, att, sk, bc, bs, out, outh, doRelu);
}

extern "C" void kernel_launch(void* const* d_in, const int* in_sizes, int n_in,
                              void* d_out, int out_size) {
    const float* x  = (const float*)d_in[0];
    const int*   ei = (const int*)d_in[1];
    const int* src = ei;
    const int* dst = ei + N_EDGES;

    const float* Wl[3]  = {(const float*)d_in[2],  (const float*)d_in[8],  (const float*)d_in[14]};
    const float* Wr[3]  = {(const float*)d_in[3],  (const float*)d_in[9],  (const float*)d_in[15]};
    const float* att[3] = {(const float*)d_in[4],  (const float*)d_in[10], (const float*)d_in[16]};
    const float* bc[3]  = {(const float*)d_in[5],  (const float*)d_in[11], (const float*)d_in[17]};
    const float* Ws[3]  = {(const float*)d_in[6],  (const float*)d_in[12], (const float*)d_in[18]};
    const float* bs[3]  = {(const float*)d_in[7],  (const float*)d_in[13], (const float*)d_in[19]};

    float *xr, *sk;
    __half *xlh, *h1h, *h2h, *xah, *wth;
    cudaGetSymbolAddress((void**)&xlh, g_xlh);
    cudaGetSymbolAddress((void**)&xr,  g_xr);
    cudaGetSymbolAddress((void**)&sk,  g_sk);
    cudaGetSymbolAddress((void**)&h1h, g_h1h);
    cudaGetSymbolAddress((void**)&h2h, g_h2h);
    cudaGetSymbolAddress((void**)&xah, g_xah);
    cudaGetSymbolAddress((void**)&wth, g_wth);

    (void)cudaFuncSetAttribute(gemm_f16_b3_kernel<128, 8>,
                               cudaFuncAttributeMaxDynamicSharedMemorySize, GEMM_SMEM(128));
    (void)cudaFuncSetAttribute(gemm_f16_b3_kernel<64, 4>,
                               cudaFuncAttributeMaxDynamicSharedMemorySize, GEMM_SMEM(64));

    // merged prepass (one launch): transpose+fp16 weights, fp16 x, zero counts
    int wK[9] = {256, 256, 256, 512, 512, 512, 256, 256, 256};
    int wN[9] = {512, 512, 512, 256, 256, 256, 128, 128, 128};
    const float* wsrc[9] = {Wl[0], Wr[0], Ws[0], Wl[1], Wr[1], Ws[1], Wl[2], Wr[2], Ws[2]};
    __half* wdst[9];
    {
        int off = 0;
        for (int i = 0; i < 9; i++) { wdst[i] = wth + off; off += wK[i] * wN[i]; }
    }
    PrepArgs pa;
    for (int i = 0; i < 9; i++) {
        pa.wsrc[i] = wsrc[i]; pa.wdst[i] = wdst[i];
        pa.K[i] = wK[i]; pa.N[i] = wN[i];
    }
    pa.xsrc = x; pa.xdst = xah; pa.xn4 = N_NODES * 256 / 4;
    prep_kernel<<<dim3(160, 11), 256>>>(pa);

    // CSR build (counting sort of edges by dst)
    hist_kernel<<<(N_EDGES + 255) / 256, 256>>>(dst);
    scan_kernel<<<1, 1024>>>();
    scatter_kernel<<<(N_EDGES + 255) / 256, 256>>>(src, dst);

    // Layer 1: 256 -> 512, relu, fp16 out for next GEMM
    run_layer(xah, 256, 512, wdst[0], wdst[1], wdst[2], att[0], bc[0], bs[0],
              nullptr, h1h, 1, xlh, xr, sk);
    // Layer 2: 512 -> 256, relu, fp16 out
    run_layer(h1h, 512, 256, wdst[3], wdst[4], wdst[5], att[1], bc[1], bs[1],
              nullptr, h2h, 1, xlh, xr, sk);
    // Layer 3: 256 -> 128, no relu, fp32 output
    run_layer(h2h, 256, 128, wdst[6], wdst[7], wdst[8], att[2], bc[2], bs[2],
              (float*)d_out, nullptr, 0, xlh, xr, sk);
}